// round 14
// baseline (speedup 1.0000x reference)
#include <cuda_runtime.h>
#include <cuda_bf16.h>
#include <math.h>
#include <stdint.h>

#define NN 50000
#define NE_MAX 800000
#define HID 128
#define NG 512

// ---------------- scratch (static __device__, no runtime alloc) ----------------
__device__ float g_x[NN * HID];
__device__ float g_h[NN * HID];
__device__ float g_pool[NG * HID];
__device__ float g_EW[100 * HID];
__device__ float g_Wpc[4 * HID];
__device__ int   g_deg[NN];
__device__ int   g_off[NN + 1];
__device__ int   g_cur[NN];
__device__ int   g_srcs[NE_MAX];
__device__ __nv_bfloat16 g_whi[8 * HID * HID];
__device__ __nv_bfloat16 g_wlo[8 * HID * HID];
__device__ int g_bar1, g_bar2;
__device__ volatile int g_flag1, g_flag2;

__device__ __forceinline__ float softplusf(float x) {
    return fmaxf(x, 0.f) + log1pf(expf(-fabsf(x)));
}

__device__ __forceinline__ void red_add_v2(float* p, float a, float b) {
    asm volatile("red.global.add.v2.f32 [%0], {%1, %2};"
                 :: "l"(p), "f"(a), "f"(b) : "memory");
}

__device__ __forceinline__ uint32_t smem_u32(const void* p) {
    uint32_t a;
    asm("{ .reg .u64 t; cvta.to.shared.u64 t, %1; cvt.u32.u64 %0, t; }" : "=r"(a) : "l"(p));
    return a;
}

#define LDSM_X4(r0, r1, r2, r3, addr) \
    asm volatile("ldmatrix.sync.aligned.m8n8.x4.shared.b16 {%0,%1,%2,%3}, [%4];" \
                 : "=r"(r0), "=r"(r1), "=r"(r2), "=r"(r3) : "r"(addr))

#define MMA16816(c, a, b0, b1) \
    asm volatile("mma.sync.aligned.m16n8k16.row.col.f32.bf16.bf16.f32 " \
                 "{%0,%1,%2,%3}, {%4,%5,%6,%7}, {%8,%9}, {%0,%1,%2,%3};" \
                 : "+f"((c)[0]), "+f"((c)[1]), "+f"((c)[2]), "+f"((c)[3]) \
                 : "r"((a)[0]), "r"((a)[1]), "r"((a)[2]), "r"((a)[3]), "r"(b0), "r"(b1))

#define CP_ASYNC16(dst, src) \
    asm volatile("cp.async.ca.shared.global [%0], [%1], 16;" :: "r"(dst), "l"(src))
#define CP_COMMIT() asm volatile("cp.async.commit_group;" ::: "memory")
#define CP_WAIT0()  asm volatile("cp.async.wait_group 0;" ::: "memory")

// ---------------- merged zero + prep (also resets barrier state) ---------------
__global__ void zero_prep_kernel(const float* __restrict__ embed_tab,
                                 const float* __restrict__ W_pos,
                                 const float* __restrict__ b_pos,
                                 const float* __restrict__ W_comb,
                                 const float* __restrict__ b_comb,
                                 const float* __restrict__ W1all,
                                 const float* __restrict__ W2all) {
    int blk = blockIdx.x;
    if (blk == 0 && threadIdx.x == 0) {
        g_bar1 = 0; g_bar2 = 0; g_flag1 = 0; g_flag2 = 0;
    }
    if (blk < 256) {
        int i = blk * 256 + threadIdx.x;
        if (i < NN) g_deg[i] = 0;
        if (i < NG * HID) g_pool[i] = 0.f;
        return;
    }
    if (threadIdx.x >= 128) return;
    int b = blk - 256;
    int j = threadIdx.x;
    if (b < 100) {
        float acc = 0.f;
        #pragma unroll 8
        for (int i = 0; i < HID; i++)
            acc += embed_tab[b * HID + i] * W_comb[i * HID + j];
        g_EW[b * HID + j] = acc;
    } else if (b == 100) {
        float a0 = 0.f, a1 = 0.f, a2 = 0.f, ab = 0.f;
        #pragma unroll 8
        for (int i = 0; i < HID; i++) {
            float w = W_comb[(HID + i) * HID + j];
            a0 += W_pos[i] * w;
            a1 += W_pos[HID + i] * w;
            a2 += W_pos[2 * HID + i] * w;
            ab += b_pos[i] * w;
        }
        g_Wpc[j]           = a0;
        g_Wpc[HID + j]     = a1;
        g_Wpc[2 * HID + j] = a2;
        g_Wpc[3 * HID + j] = ab + b_comb[j];
    } else {
        int mat = b - 101;
        const float* W = ((mat & 1) ? W2all : W1all) + (size_t)(mat >> 1) * HID * HID;
        __nv_bfloat16* hi = g_whi + (size_t)mat * HID * HID;
        __nv_bfloat16* lo = g_wlo + (size_t)mat * HID * HID;
        #pragma unroll 4
        for (int k = 0; k < HID; k++) {
            float w = W[k * HID + j];
            __nv_bfloat16 hh = __float2bfloat16(w);
            hi[j * HID + k] = hh;
            lo[j * HID + k] = __float2bfloat16(w - __bfloat162float(hh));
        }
    }
}

// ======== persistent CSR build + x0: (hist|x0) -> scan -> fill =================
#define CSR_BLOCKS 1184

__global__ __launch_bounds__(256, 8)
void csr_x0_kernel(const int* __restrict__ src, const int* __restrict__ dst, int E,
                   const int* __restrict__ z, const float* __restrict__ pos, int N) {
    int tid = threadIdx.x;
    const int C = (E + 3) / 4;

    // ---- phase 1a: degree histogram ----
    for (int i = blockIdx.x * 256 + tid; i < C; i += gridDim.x * 256) {
        int e = i * 4;
        if (e + 3 < E) {
            int4 d = ((const int4*)dst)[i];
            atomicAdd(&g_deg[d.x], 1);
            atomicAdd(&g_deg[d.y], 1);
            atomicAdd(&g_deg[d.z], 1);
            atomicAdd(&g_deg[d.w], 1);
        } else {
            for (; e < E; e++) atomicAdd(&g_deg[__ldg(dst + e)], 1);
        }
    }
    // ---- phase 1b: x0 (independent; fills barrier latency) ----
    for (int tt = blockIdx.x * 256 + tid; tt < N * 32; tt += gridDim.x * 256) {
        int n = tt >> 5, c = tt & 31;
        int zz = __ldg(z + n);
        float p0 = __ldg(pos + n * 3), p1 = __ldg(pos + n * 3 + 1), p2 = __ldg(pos + n * 3 + 2);
        float4 ew = *(const float4*)(g_EW + zz * HID + c * 4);
        float4 w0 = *(const float4*)(g_Wpc + c * 4);
        float4 w1 = *(const float4*)(g_Wpc + HID + c * 4);
        float4 w2 = *(const float4*)(g_Wpc + 2 * HID + c * 4);
        float4 bf = *(const float4*)(g_Wpc + 3 * HID + c * 4);
        float4 v;
        v.x = fmaxf(ew.x + p0 * w0.x + p1 * w1.x + p2 * w2.x + bf.x, 0.f);
        v.y = fmaxf(ew.y + p0 * w0.y + p1 * w1.y + p2 * w2.y + bf.y, 0.f);
        v.z = fmaxf(ew.z + p0 * w0.z + p1 * w1.z + p2 * w2.z + bf.z, 0.f);
        v.w = fmaxf(ew.w + p0 * w0.w + p1 * w1.w + p2 * w2.w + bf.w, 0.f);
        *(float4*)(g_x + n * HID + c * 4) = v;
    }

    // ---- barrier 1 ----
    __threadfence();
    __syncthreads();
    if (tid == 0) {
        if (atomicAdd(&g_bar1, 1) == gridDim.x - 1) g_flag1 = 1;
        else while (g_flag1 == 0) { }
    }
    __syncthreads();

    // ---- phase 2: exclusive scan (block 0) ----
    if (blockIdx.x == 0) {
        __shared__ int part[256];
        const int CH = (NN + 255) / 256;
        int base = tid * CH;
        int s = 0;
        for (int k = 0; k < CH; k++) {
            int idx = base + k;
            if (idx < NN) s += g_deg[idx];
        }
        part[tid] = s;
        __syncthreads();
        for (int off = 1; off < 256; off <<= 1) {
            int v = (tid >= off) ? part[tid - off] : 0;
            __syncthreads();
            part[tid] += v;
            __syncthreads();
        }
        int run = (tid == 0) ? 0 : part[tid - 1];
        for (int k = 0; k < CH; k++) {
            int idx = base + k;
            if (idx < NN) { g_off[idx] = run; g_cur[idx] = run; run += g_deg[idx]; }
        }
        if (tid == 255) g_off[NN] = run;
        __threadfence();
    }

    // ---- barrier 2 ----
    __syncthreads();
    if (tid == 0) {
        if (atomicAdd(&g_bar2, 1) == gridDim.x - 1) g_flag2 = 1;
        else while (g_flag2 == 0) { }
    }
    __syncthreads();

    // ---- phase 3: fill ----
    for (int i = blockIdx.x * 256 + tid; i < C; i += gridDim.x * 256) {
        int e = i * 4;
        if (e + 3 < E) {
            int4 s4 = ((const int4*)src)[i];
            int4 d4 = ((const int4*)dst)[i];
            int p0 = atomicAdd(&g_cur[d4.x], 1);
            int p1 = atomicAdd(&g_cur[d4.y], 1);
            int p2 = atomicAdd(&g_cur[d4.z], 1);
            int p3 = atomicAdd(&g_cur[d4.w], 1);
            g_srcs[p0] = s4.x;
            g_srcs[p1] = s4.y;
            g_srcs[p2] = s4.z;
            g_srcs[p3] = s4.w;
        } else {
            for (; e < E; e++) {
                int p = atomicAdd(&g_cur[__ldg(dst + e)], 1);
                g_srcs[p] = __ldg(src + e);
            }
        }
    }
}

// ---------------- CSR aggregation (fp32, 8-deep unroll) ------------------------
__global__ void agg_kernel(int N) {
    int tid = blockIdx.x * blockDim.x + threadIdx.x;
    int n = tid >> 5;
    if (n >= N) return;
    int lane = tid & 31;
    const float4* x4 = (const float4*)g_x;
    float4 a0 = x4[n * 32 + lane];
    float4 a1 = {0.f, 0.f, 0.f, 0.f};
    float4 a2 = {0.f, 0.f, 0.f, 0.f};
    float4 a3 = {0.f, 0.f, 0.f, 0.f};
    int beg = __ldg(&g_off[n]), end = __ldg(&g_off[n + 1]);
    int e = beg;
    for (; e + 8 <= end; e += 8) {
        int s0 = __ldg(&g_srcs[e]);
        int s1 = __ldg(&g_srcs[e + 1]);
        int s2 = __ldg(&g_srcs[e + 2]);
        int s3 = __ldg(&g_srcs[e + 3]);
        int s4 = __ldg(&g_srcs[e + 4]);
        int s5 = __ldg(&g_srcs[e + 5]);
        int s6 = __ldg(&g_srcs[e + 6]);
        int s7 = __ldg(&g_srcs[e + 7]);
        float4 v0 = x4[s0 * 32 + lane];
        float4 v1 = x4[s1 * 32 + lane];
        float4 v2 = x4[s2 * 32 + lane];
        float4 v3 = x4[s3 * 32 + lane];
        float4 v4 = x4[s4 * 32 + lane];
        float4 v5 = x4[s5 * 32 + lane];
        float4 v6 = x4[s6 * 32 + lane];
        float4 v7 = x4[s7 * 32 + lane];
        a0.x += v0.x; a0.y += v0.y; a0.z += v0.z; a0.w += v0.w;
        a1.x += v1.x; a1.y += v1.y; a1.z += v1.z; a1.w += v1.w;
        a2.x += v2.x; a2.y += v2.y; a2.z += v2.z; a2.w += v2.w;
        a3.x += v3.x; a3.y += v3.y; a3.z += v3.z; a3.w += v3.w;
        a0.x += v4.x; a0.y += v4.y; a0.z += v4.z; a0.w += v4.w;
        a1.x += v5.x; a1.y += v5.y; a1.z += v5.z; a1.w += v5.w;
        a2.x += v6.x; a2.y += v6.y; a2.z += v6.z; a2.w += v6.w;
        a3.x += v7.x; a3.y += v7.y; a3.z += v7.z; a3.w += v7.w;
    }
    for (; e < end; e++) {
        int s = __ldg(&g_srcs[e]);
        float4 v = x4[s * 32 + lane];
        a0.x += v.x; a0.y += v.y; a0.z += v.z; a0.w += v.w;
    }
    float4 r;
    r.x = a0.x + a1.x + a2.x + a3.x;
    r.y = a0.y + a1.y + a2.y + a3.y;
    r.z = a0.z + a1.z + a2.z + a3.z;
    r.w = a0.w + a1.w + a2.w + a3.w;
    ((float4*)g_h)[n * 32 + lane] = r;
}

// ========== PERSISTENT fused MLP: 64-row tiles, 2 CTAs/SM ======================
// hi-weights in SMEM; LO-WEIGHT FRAGMENTS IN REGISTERS (loaded once per CTA).
#define PAD 136
#define ATILE (64 * PAD * 2)               // 17408
#define WTILE (128 * PAD * 2)              // 34816
#define OFF_AHI 0
#define OFF_ALO ATILE
#define OFF_W1H (2 * ATILE)                // 34816
#define OFF_W2H (2 * ATILE + WTILE)        // 69632
#define SMEM_F  (2 * ATILE + 2 * WTILE)    // 104448 -> 2 CTAs/SM

template<int FINAL>
__global__ __launch_bounds__(256, 2)
void gemm_fused(const float* __restrict__ A,
                const __nv_bfloat16* __restrict__ W1h, const __nv_bfloat16* __restrict__ W1l,
                const __nv_bfloat16* __restrict__ W2h, const __nv_bfloat16* __restrict__ W2l,
                const float* __restrict__ b1, const float* __restrict__ b2,
                float* __restrict__ Cf, const int* __restrict__ batch,
                int M, int tiles) {
    extern __shared__ char smem[];
    uint32_t sb = smem_u32(smem);
    int t = threadIdx.x, wid = t >> 5, lane = t & 31;
    int warp_m = wid & 1, warp_n = wid >> 1;

    // lane addressing
    int a_r = warp_m * 32 + (lane & 15);
    int a_k = (lane >> 4) * 8;
    uint32_t aoff = (uint32_t)(a_r * PAD + a_k) * 2;
    int b_n = warp_n * 32 + (lane & 7) + ((lane >> 4) << 3);
    int b_k = ((lane >> 3) & 1) * 8;
    uint32_t boff = (uint32_t)(b_n * PAD + b_k) * 2;
    int g = lane >> 2, tq = lane & 3;

    // ---- stage 1: hi weights to homes + W1l to stage (A-tile area) ----
    #pragma unroll
    for (int i = 0; i < 8; i++) {
        int idx = i * 256 + t;
        int n = idx >> 4, k8 = idx & 15;
        uint32_t off = (uint32_t)(n * PAD + k8 * 8) * 2;
        CP_ASYNC16(sb + OFF_W1H + off, (const char*)W1h + idx * 16);
        CP_ASYNC16(sb + OFF_W2H + off, (const char*)W2h + idx * 16);
        CP_ASYNC16(sb + OFF_AHI + off, (const char*)W1l + idx * 16);
    }
    CP_COMMIT();
    CP_WAIT0();
    __syncthreads();

    uint32_t w1l[8][2][4];
    #pragma unroll
    for (int ks = 0; ks < 8; ks++)
        #pragma unroll
        for (int nb = 0; nb < 2; nb++) {
            uint32_t bd = sb + OFF_AHI + boff + (uint32_t)(nb * 16 * PAD) * 2 + ks * 32;
            LDSM_X4(w1l[ks][nb][0], w1l[ks][nb][1], w1l[ks][nb][2], w1l[ks][nb][3], bd);
        }
    __syncthreads();

    // ---- stage 2: W2l to stage ----
    #pragma unroll
    for (int i = 0; i < 8; i++) {
        int idx = i * 256 + t;
        int n = idx >> 4, k8 = idx & 15;
        uint32_t off = (uint32_t)(n * PAD + k8 * 8) * 2;
        CP_ASYNC16(sb + OFF_AHI + off, (const char*)W2l + idx * 16);
    }
    CP_COMMIT();
    CP_WAIT0();
    __syncthreads();

    uint32_t w2l[8][2][4];
    #pragma unroll
    for (int ks = 0; ks < 8; ks++)
        #pragma unroll
        for (int nb = 0; nb < 2; nb++) {
            uint32_t bd = sb + OFF_AHI + boff + (uint32_t)(nb * 16 * PAD) * 2 + ks * 32;
            LDSM_X4(w2l[ks][nb][0], w2l[ks][nb][1], w2l[ks][nb][2], w2l[ks][nb][3], bd);
        }

    for (int tile = blockIdx.x; tile < tiles; tile += gridDim.x) {
        int row0 = tile * 64;
        __syncthreads();                   // prior reads of A bufs (or w2l stage) done

        // ---- A: load f32, split bf16 hi/lo (64 rows) ----
        #pragma unroll
        for (int i = 0; i < 4; i++) {
            int idx = i * 256 + t;         // 1024 chunks: r=idx>>4, k8=idx&15
            int r = idx >> 4, k8 = idx & 15;
            int row = row0 + r;
            if (row >= M) row = M - 1;
            const float4* ap = (const float4*)(A + (size_t)row * HID + k8 * 8);
            float4 aA = ap[0], aB = ap[1];
            __nv_bfloat162 h0 = __floats2bfloat162_rn(aA.x, aA.y);
            __nv_bfloat162 h1 = __floats2bfloat162_rn(aA.z, aA.w);
            __nv_bfloat162 h2 = __floats2bfloat162_rn(aB.x, aB.y);
            __nv_bfloat162 h3 = __floats2bfloat162_rn(aB.z, aB.w);
            __nv_bfloat162 l0 = __floats2bfloat162_rn(aA.x - __bfloat162float(h0.x), aA.y - __bfloat162float(h0.y));
            __nv_bfloat162 l1 = __floats2bfloat162_rn(aA.z - __bfloat162float(h1.x), aA.w - __bfloat162float(h1.y));
            __nv_bfloat162 l2 = __floats2bfloat162_rn(aB.x - __bfloat162float(h2.x), aB.y - __bfloat162float(h2.y));
            __nv_bfloat162 l3 = __floats2bfloat162_rn(aB.z - __bfloat162float(h3.x), aB.w - __bfloat162float(h3.y));
            uint4 hv = {*(uint32_t*)&h0, *(uint32_t*)&h1, *(uint32_t*)&h2, *(uint32_t*)&h3};
            uint4 lv = {*(uint32_t*)&l0, *(uint32_t*)&l1, *(uint32_t*)&l2, *(uint32_t*)&l3};
            uint32_t off = (uint32_t)(r * PAD + k8 * 8) * 2;
            *(uint4*)(smem + OFF_AHI + off) = hv;
            *(uint4*)(smem + OFF_ALO + off) = lv;
        }
        __syncthreads();

        float acc[2][4][4];

        // ---- mainloop 1: h @ W1 ----
        #pragma unroll
        for (int i = 0; i < 2; i++)
            #pragma unroll
            for (int j = 0; j < 4; j++)
                acc[i][j][0] = acc[i][j][1] = acc[i][j][2] = acc[i][j][3] = 0.f;

        #pragma unroll
        for (int ks = 0; ks < 8; ks++) {
            uint32_t kb = (uint32_t)(ks * 16) * 2;
            uint32_t ah[2][4], al[2][4], bh[2][4];
            #pragma unroll
            for (int mt = 0; mt < 2; mt++) {
                uint32_t ad = sb + aoff + (uint32_t)(mt * 16 * PAD) * 2 + kb;
                LDSM_X4(ah[mt][0], ah[mt][1], ah[mt][2], ah[mt][3], ad + OFF_AHI);
                LDSM_X4(al[mt][0], al[mt][1], al[mt][2], al[mt][3], ad + OFF_ALO);
            }
            #pragma unroll
            for (int nb = 0; nb < 2; nb++) {
                uint32_t bd = sb + OFF_W1H + boff + (uint32_t)(nb * 16 * PAD) * 2 + kb;
                LDSM_X4(bh[nb][0], bh[nb][1], bh[nb][2], bh[nb][3], bd);
            }
            #pragma unroll
            for (int mt = 0; mt < 2; mt++) {
                #pragma unroll
                for (int nt = 0; nt < 4; nt++) {
                    int nb = nt >> 1, h = (nt & 1) * 2;
                    MMA16816(acc[mt][nt], ah[mt], bh[nb][h], bh[nb][h + 1]);
                    MMA16816(acc[mt][nt], ah[mt], w1l[ks][nb][h], w1l[ks][nb][h + 1]);
                    MMA16816(acc[mt][nt], al[mt], bh[nb][h], bh[nb][h + 1]);
                }
            }
        }

        // ---- bias1 + relu + split -> overwrite A buffers as T ----
        __syncthreads();
        #pragma unroll
        for (int mt = 0; mt < 2; mt++) {
            int rloc = warp_m * 32 + mt * 16 + g;
            #pragma unroll
            for (int nt = 0; nt < 4; nt++) {
                int col = warp_n * 32 + nt * 8 + tq * 2;
                float bx = __ldg(b1 + col), by = __ldg(b1 + col + 1);
                float v0 = fmaxf(acc[mt][nt][0] + bx, 0.f);
                float v1 = fmaxf(acc[mt][nt][1] + by, 0.f);
                float v2 = fmaxf(acc[mt][nt][2] + bx, 0.f);
                float v3 = fmaxf(acc[mt][nt][3] + by, 0.f);
                __nv_bfloat162 hA = __floats2bfloat162_rn(v0, v1);
                __nv_bfloat162 lA = __floats2bfloat162_rn(v0 - __bfloat162float(hA.x),
                                                          v1 - __bfloat162float(hA.y));
                __nv_bfloat162 hB = __floats2bfloat162_rn(v2, v3);
                __nv_bfloat162 lB = __floats2bfloat162_rn(v2 - __bfloat162float(hB.x),
                                                          v3 - __bfloat162float(hB.y));
                uint32_t o0 = (uint32_t)(rloc * PAD + col) * 2;
                uint32_t o1 = (uint32_t)((rloc + 8) * PAD + col) * 2;
                *(uint32_t*)(smem + OFF_AHI + o0) = *(uint32_t*)&hA;
                *(uint32_t*)(smem + OFF_ALO + o0) = *(uint32_t*)&lA;
                *(uint32_t*)(smem + OFF_AHI + o1) = *(uint32_t*)&hB;
                *(uint32_t*)(smem + OFF_ALO + o1) = *(uint32_t*)&lB;
            }
        }
        __syncthreads();

        // ---- mainloop 2: T @ W2 ----
        #pragma unroll
        for (int i = 0; i < 2; i++)
            #pragma unroll
            for (int j = 0; j < 4; j++)
                acc[i][j][0] = acc[i][j][1] = acc[i][j][2] = acc[i][j][3] = 0.f;

        #pragma unroll
        for (int ks = 0; ks < 8; ks++) {
            uint32_t kb = (uint32_t)(ks * 16) * 2;
            uint32_t ah[2][4], al[2][4], bh[2][4];
            #pragma unroll
            for (int mt = 0; mt < 2; mt++) {
                uint32_t ad = sb + aoff + (uint32_t)(mt * 16 * PAD) * 2 + kb;
                LDSM_X4(ah[mt][0], ah[mt][1], ah[mt][2], ah[mt][3], ad + OFF_AHI);
                LDSM_X4(al[mt][0], al[mt][1], al[mt][2], al[mt][3], ad + OFF_ALO);
            }
            #pragma unroll
            for (int nb = 0; nb < 2; nb++) {
                uint32_t bd = sb + OFF_W2H + boff + (uint32_t)(nb * 16 * PAD) * 2 + kb;
                LDSM_X4(bh[nb][0], bh[nb][1], bh[nb][2], bh[nb][3], bd);
            }
            #pragma unroll
            for (int mt = 0; mt < 2; mt++) {
                #pragma unroll
                for (int nt = 0; nt < 4; nt++) {
                    int nb = nt >> 1, h = (nt & 1) * 2;
                    MMA16816(acc[mt][nt], ah[mt], bh[nb][h], bh[nb][h + 1]);
                    MMA16816(acc[mt][nt], ah[mt], w2l[ks][nb][h], w2l[ks][nb][h + 1]);
                    MMA16816(acc[mt][nt], al[mt], bh[nb][h], bh[nb][h + 1]);
                }
            }
        }

        // ---- epilogue ----
        #pragma unroll
        for (int mt = 0; mt < 2; mt++) {
            int rbase = row0 + warp_m * 32 + mt * 16 + g;
            #pragma unroll
            for (int nt = 0; nt < 4; nt++) {
                int col = warp_n * 32 + nt * 8 + tq * 2;
                float bx = __ldg(b2 + col), by = __ldg(b2 + col + 1);
                float v0 = acc[mt][nt][0] + bx, v1 = acc[mt][nt][1] + by;
                float v2 = acc[mt][nt][2] + bx, v3 = acc[mt][nt][3] + by;
                if (FINAL == 0) {
                    v0 = fmaxf(v0, 0.f); v1 = fmaxf(v1, 0.f);
                    v2 = fmaxf(v2, 0.f); v3 = fmaxf(v3, 0.f);
                    if (rbase < M)
                        *(float2*)(Cf + (size_t)rbase * HID + col) = make_float2(v0, v1);
                    if (rbase + 8 < M)
                        *(float2*)(Cf + (size_t)(rbase + 8) * HID + col) = make_float2(v2, v3);
                } else {
                    if (rbase < M)
                        red_add_v2(g_pool + __ldg(batch + rbase) * HID + col, v0, v1);
                    if (rbase + 8 < M)
                        red_add_v2(g_pool + __ldg(batch + rbase + 8) * HID + col, v2, v3);
                }
            }
        }
    }
}

// ---------------- heads ---------------------------------------------------------
__global__ void heads_kernel(const float* __restrict__ W1, const float* __restrict__ b1,
                             const float* __restrict__ W2, const float* __restrict__ b2,
                             float* __restrict__ out) {
    __shared__ float sa[HID];
    __shared__ float red[HID];
    __shared__ float o[4];
    int g = blockIdx.x, j = threadIdx.x;
    sa[j] = g_pool[g * HID + j];
    __syncthreads();
    for (int k = 0; k < 4; k++) {
        float acc = b1[k * HID + j];
        const float* w = W1 + k * HID * HID + j;
        #pragma unroll 8
        for (int i = 0; i < HID; i++) acc += sa[i] * w[i * HID];
        acc = fmaxf(acc, 0.f);
        red[j] = acc * W2[k * HID + j];
        __syncthreads();
        for (int s = 64; s > 0; s >>= 1) {
            if (j < s) red[j] += red[j + s];
            __syncthreads();
        }
        if (j == 0) o[k] = red[0] + b2[k];
        __syncthreads();
    }
    if (j == 0) {
        float alpha = fmaxf(softplusf(o[0]) + 1.f, 1.f + 1e-4f);
        float beta  = softplusf(o[1]);
        float nu    = softplusf(o[2]);
        float gamma = o[3];
        float am1 = alpha - 1.f;
        out[g]            = gamma;
        out[NG + g]       = beta / am1;
        out[2 * NG + g]   = beta / (am1 * nu);
        out[3 * NG + g]   = nu;
        out[4 * NG + g]   = alpha;
        out[5 * NG + g]   = beta;
    }
}

// ---------------- driver --------------------------------------------------------
extern "C" void kernel_launch(void* const* d_in, const int* in_sizes, int n_in,
                              void* d_out, int out_size) {
    const int*   z        = (const int*)d_in[0];
    const float* pos      = (const float*)d_in[1];
    const int*   batch    = (const int*)d_in[2];
    const int*   eidx     = (const int*)d_in[3];
    const float* embed    = (const float*)d_in[4];
    const float* W_pos    = (const float*)d_in[5];
    const float* b_pos    = (const float*)d_in[6];
    const float* W_comb   = (const float*)d_in[7];
    const float* b_comb   = (const float*)d_in[8];
    const float* gin_W1   = (const float*)d_in[9];
    const float* gin_b1   = (const float*)d_in[10];
    const float* gin_W2   = (const float*)d_in[11];
    const float* gin_b2   = (const float*)d_in[12];
    const float* head_W1  = (const float*)d_in[13];
    const float* head_b1  = (const float*)d_in[14];
    const float* head_W2  = (const float*)d_in[15];
    const float* head_b2  = (const float*)d_in[16];
    float* out = (float*)d_out;

    const int N = in_sizes[0];
    const int E = in_sizes[3] / 2;
    const int* src = eidx;
    const int* dst = eidx + E;

    float *x, *h;
    __nv_bfloat16 *whi, *wlo;
    cudaGetSymbolAddress((void**)&x, g_x);
    cudaGetSymbolAddress((void**)&h, g_h);
    cudaGetSymbolAddress((void**)&whi, g_whi);
    cudaGetSymbolAddress((void**)&wlo, g_wlo);

    cudaFuncSetAttribute(gemm_fused<0>, cudaFuncAttributeMaxDynamicSharedMemorySize, SMEM_F);
    cudaFuncSetAttribute(gemm_fused<1>, cudaFuncAttributeMaxDynamicSharedMemorySize, SMEM_F);

    // 1. zero+prep (1), persistent CSR+x0 (2)
    zero_prep_kernel<<<365, 256>>>(embed, W_pos, b_pos, W_comb, b_comb, gin_W1, gin_W2);
    csr_x0_kernel<<<CSR_BLOCKS, 256>>>(src, dst, E, z, pos, N);

    // 2. GIN layers — agg(3), layer-0 gemm is launch #4 (ncu capture slot)
    const int tiles = (N + 63) / 64;
    const int pblocks = (tiles < 296) ? tiles : 296;   // 2 CTAs/SM
    const int agg_blocks = (N * 32 + 255) / 256;
    for (int l = 0; l < 4; l++) {
        agg_kernel<<<agg_blocks, 256>>>(N);
        const __nv_bfloat16* w1h = whi + (size_t)(2 * l) * HID * HID;
        const __nv_bfloat16* w1l = wlo + (size_t)(2 * l) * HID * HID;
        const __nv_bfloat16* w2h = whi + (size_t)(2 * l + 1) * HID * HID;
        const __nv_bfloat16* w2l = wlo + (size_t)(2 * l + 1) * HID * HID;
        if (l < 3)
            gemm_fused<0><<<pblocks, 256, SMEM_F>>>(h, w1h, w1l, w2h, w2l,
                                                    gin_b1 + l * HID, gin_b2 + l * HID,
                                                    x, nullptr, N, tiles);
        else
            gemm_fused<1><<<pblocks, 256, SMEM_F>>>(h, w1h, w1l, w2h, w2l,
                                                    gin_b1 + l * HID, gin_b2 + l * HID,
                                                    nullptr, batch, N, tiles);
    }

    // 3. heads
    heads_kernel<<<NG, 128>>>(head_W1, head_b1, head_W2, head_b2, out);
}

// round 15
// speedup vs baseline: 1.0214x; 1.0214x over previous
#include <cuda_runtime.h>
#include <cuda_bf16.h>
#include <math.h>
#include <stdint.h>

#define NN 50000
#define NE_MAX 800000
#define HID 128
#define NG 512

// ---------------- scratch (static __device__, no runtime alloc) ----------------
__device__ float g_x[NN * HID];
__device__ float g_h[NN * HID];
__device__ float g_pool[NG * HID];
__device__ float g_EW[100 * HID];
__device__ float g_Wpc[4 * HID];
__device__ int   g_deg[NN];
__device__ int   g_off[NN + 1];
__device__ int   g_cur[NN];
__device__ int   g_srcs[NE_MAX];
__device__ __nv_bfloat16 g_whi[8 * HID * HID];
__device__ __nv_bfloat16 g_wlo[8 * HID * HID];

__device__ __forceinline__ float softplusf(float x) {
    return fmaxf(x, 0.f) + log1pf(expf(-fabsf(x)));
}

__device__ __forceinline__ void red_add_v2(float* p, float a, float b) {
    asm volatile("red.global.add.v2.f32 [%0], {%1, %2};"
                 :: "l"(p), "f"(a), "f"(b) : "memory");
}

__device__ __forceinline__ uint32_t smem_u32(const void* p) {
    uint32_t a;
    asm("{ .reg .u64 t; cvta.to.shared.u64 t, %1; cvt.u32.u64 %0, t; }" : "=r"(a) : "l"(p));
    return a;
}

#define LDSM_X4(r0, r1, r2, r3, addr) \
    asm volatile("ldmatrix.sync.aligned.m8n8.x4.shared.b16 {%0,%1,%2,%3}, [%4];" \
                 : "=r"(r0), "=r"(r1), "=r"(r2), "=r"(r3) : "r"(addr))

#define MMA16816(c, a, b0, b1) \
    asm volatile("mma.sync.aligned.m16n8k16.row.col.f32.bf16.bf16.f32 " \
                 "{%0,%1,%2,%3}, {%4,%5,%6,%7}, {%8,%9}, {%0,%1,%2,%3};" \
                 : "+f"((c)[0]), "+f"((c)[1]), "+f"((c)[2]), "+f"((c)[3]) \
                 : "r"((a)[0]), "r"((a)[1]), "r"((a)[2]), "r"((a)[3]), "r"(b0), "r"(b1))

#define CP_ASYNC16(dst, src) \
    asm volatile("cp.async.ca.shared.global [%0], [%1], 16;" :: "r"(dst), "l"(src))
#define CP_COMMIT() asm volatile("cp.async.commit_group;" ::: "memory")
#define CP_WAIT0()  asm volatile("cp.async.wait_group 0;" ::: "memory")

// ================= CSR build (separate kernels — no spin barriers) =============
__global__ void zero_kernel() {
    int i = blockIdx.x * blockDim.x + threadIdx.x;
    if (i < NN) g_deg[i] = 0;
    if (i < NG * HID) g_pool[i] = 0.f;
}

__global__ void hist_kernel(const int* __restrict__ dst, int E) {
    int i = blockIdx.x * blockDim.x + threadIdx.x;
    int e = i * 4;
    if (e + 3 < E) {
        int4 d = ((const int4*)dst)[i];
        atomicAdd(&g_deg[d.x], 1);
        atomicAdd(&g_deg[d.y], 1);
        atomicAdd(&g_deg[d.z], 1);
        atomicAdd(&g_deg[d.w], 1);
    } else {
        for (; e < E; e++) atomicAdd(&g_deg[__ldg(dst + e)], 1);
    }
}

__global__ void scan_kernel() {
    __shared__ int part[1024];
    int t = threadIdx.x;
    const int CH = (NN + 1023) / 1024;
    int base = t * CH;
    int s = 0;
    #pragma unroll 8
    for (int i = 0; i < CH; i++) { int idx = base + i; if (idx < NN) s += g_deg[idx]; }
    part[t] = s;
    __syncthreads();
    for (int off = 1; off < 1024; off <<= 1) {
        int v = (t >= off) ? part[t - off] : 0;
        __syncthreads();
        part[t] += v;
        __syncthreads();
    }
    int run = (t == 0) ? 0 : part[t - 1];
    #pragma unroll 8
    for (int i = 0; i < CH; i++) {
        int idx = base + i;
        if (idx < NN) { g_off[idx] = run; g_cur[idx] = run; run += g_deg[idx]; }
    }
    if (t == 1023) g_off[NN] = run;
}

__global__ void fill_kernel(const int* __restrict__ src, const int* __restrict__ dst, int E) {
    int i = blockIdx.x * blockDim.x + threadIdx.x;
    int e = i * 4;
    if (e + 3 < E) {
        int4 s = ((const int4*)src)[i];
        int4 d = ((const int4*)dst)[i];
        int p0 = atomicAdd(&g_cur[d.x], 1);
        int p1 = atomicAdd(&g_cur[d.y], 1);
        int p2 = atomicAdd(&g_cur[d.z], 1);
        int p3 = atomicAdd(&g_cur[d.w], 1);
        g_srcs[p0] = s.x;
        g_srcs[p1] = s.y;
        g_srcs[p2] = s.z;
        g_srcs[p3] = s.w;
    } else {
        for (; e < E; e++) {
            int p = atomicAdd(&g_cur[__ldg(dst + e)], 1);
            g_srcs[p] = __ldg(src + e);
        }
    }
}

// ---------------- prep: fold embedding algebra + split/transpose weights -------
__global__ void prep_kernel(const float* __restrict__ embed_tab,
                            const float* __restrict__ W_pos,
                            const float* __restrict__ b_pos,
                            const float* __restrict__ W_comb,
                            const float* __restrict__ b_comb,
                            const float* __restrict__ W1all,
                            const float* __restrict__ W2all) {
    int j = threadIdx.x;
    int b = blockIdx.x;
    if (b < 100) {
        float acc = 0.f;
        #pragma unroll 8
        for (int i = 0; i < HID; i++)
            acc += embed_tab[b * HID + i] * W_comb[i * HID + j];
        g_EW[b * HID + j] = acc;
    } else if (b == 100) {
        float a0 = 0.f, a1 = 0.f, a2 = 0.f, ab = 0.f;
        #pragma unroll 8
        for (int i = 0; i < HID; i++) {
            float w = W_comb[(HID + i) * HID + j];
            a0 += W_pos[i] * w;
            a1 += W_pos[HID + i] * w;
            a2 += W_pos[2 * HID + i] * w;
            ab += b_pos[i] * w;
        }
        g_Wpc[j]           = a0;
        g_Wpc[HID + j]     = a1;
        g_Wpc[2 * HID + j] = a2;
        g_Wpc[3 * HID + j] = ab + b_comb[j];
    } else {
        int mat = b - 101;
        const float* W = ((mat & 1) ? W2all : W1all) + (size_t)(mat >> 1) * HID * HID;
        __nv_bfloat16* hi = g_whi + (size_t)mat * HID * HID;
        __nv_bfloat16* lo = g_wlo + (size_t)mat * HID * HID;
        #pragma unroll 4
        for (int k = 0; k < HID; k++) {
            float w = W[k * HID + j];
            __nv_bfloat16 hh = __float2bfloat16(w);
            hi[j * HID + k] = hh;
            lo[j * HID + k] = __float2bfloat16(w - __bfloat162float(hh));
        }
    }
}

// ---------------- x0 = relu(EW[z] + pos@Wpc + bfuse) ---------------------------
__global__ void x0_kernel(const int* __restrict__ z, const float* __restrict__ pos, int N) {
    int tid = blockIdx.x * blockDim.x + threadIdx.x;
    int n = tid >> 5;
    if (n >= N) return;
    int c = tid & 31;
    int zz = __ldg(z + n);
    float p0 = __ldg(pos + n * 3), p1 = __ldg(pos + n * 3 + 1), p2 = __ldg(pos + n * 3 + 2);
    float4 ew = *(const float4*)(g_EW + zz * HID + c * 4);
    float4 w0 = *(const float4*)(g_Wpc + c * 4);
    float4 w1 = *(const float4*)(g_Wpc + HID + c * 4);
    float4 w2 = *(const float4*)(g_Wpc + 2 * HID + c * 4);
    float4 bf = *(const float4*)(g_Wpc + 3 * HID + c * 4);
    float4 v;
    v.x = fmaxf(ew.x + p0 * w0.x + p1 * w1.x + p2 * w2.x + bf.x, 0.f);
    v.y = fmaxf(ew.y + p0 * w0.y + p1 * w1.y + p2 * w2.y + bf.y, 0.f);
    v.z = fmaxf(ew.z + p0 * w0.z + p1 * w1.z + p2 * w2.z + bf.z, 0.f);
    v.w = fmaxf(ew.w + p0 * w0.w + p1 * w1.w + p2 * w2.w + bf.w, 0.f);
    *(float4*)(g_x + n * HID + c * 4) = v;
}

// ---------------- CSR aggregation (fp32, 8-deep unroll) ------------------------
__global__ void agg_kernel(int N) {
    int tid = blockIdx.x * blockDim.x + threadIdx.x;
    int n = tid >> 5;
    if (n >= N) return;
    int lane = tid & 31;
    const float4* x4 = (const float4*)g_x;
    float4 a0 = x4[n * 32 + lane];
    float4 a1 = {0.f, 0.f, 0.f, 0.f};
    float4 a2 = {0.f, 0.f, 0.f, 0.f};
    float4 a3 = {0.f, 0.f, 0.f, 0.f};
    int beg = __ldg(&g_off[n]), end = __ldg(&g_off[n + 1]);
    int e = beg;
    for (; e + 8 <= end; e += 8) {
        int s0 = __ldg(&g_srcs[e]);
        int s1 = __ldg(&g_srcs[e + 1]);
        int s2 = __ldg(&g_srcs[e + 2]);
        int s3 = __ldg(&g_srcs[e + 3]);
        int s4 = __ldg(&g_srcs[e + 4]);
        int s5 = __ldg(&g_srcs[e + 5]);
        int s6 = __ldg(&g_srcs[e + 6]);
        int s7 = __ldg(&g_srcs[e + 7]);
        float4 v0 = x4[s0 * 32 + lane];
        float4 v1 = x4[s1 * 32 + lane];
        float4 v2 = x4[s2 * 32 + lane];
        float4 v3 = x4[s3 * 32 + lane];
        float4 v4 = x4[s4 * 32 + lane];
        float4 v5 = x4[s5 * 32 + lane];
        float4 v6 = x4[s6 * 32 + lane];
        float4 v7 = x4[s7 * 32 + lane];
        a0.x += v0.x; a0.y += v0.y; a0.z += v0.z; a0.w += v0.w;
        a1.x += v1.x; a1.y += v1.y; a1.z += v1.z; a1.w += v1.w;
        a2.x += v2.x; a2.y += v2.y; a2.z += v2.z; a2.w += v2.w;
        a3.x += v3.x; a3.y += v3.y; a3.z += v3.z; a3.w += v3.w;
        a0.x += v4.x; a0.y += v4.y; a0.z += v4.z; a0.w += v4.w;
        a1.x += v5.x; a1.y += v5.y; a1.z += v5.z; a1.w += v5.w;
        a2.x += v6.x; a2.y += v6.y; a2.z += v6.z; a2.w += v6.w;
        a3.x += v7.x; a3.y += v7.y; a3.z += v7.z; a3.w += v7.w;
    }
    for (; e < end; e++) {
        int s = __ldg(&g_srcs[e]);
        float4 v = x4[s * 32 + lane];
        a0.x += v.x; a0.y += v.y; a0.z += v.z; a0.w += v.w;
    }
    float4 r;
    r.x = a0.x + a1.x + a2.x + a3.x;
    r.y = a0.y + a1.y + a2.y + a3.y;
    r.z = a0.z + a1.z + a2.z + a3.z;
    r.w = a0.w + a1.w + a2.w + a3.w;
    ((float4*)g_h)[n * 32 + lane] = r;
}

// ========== PERSISTENT fused MLP: 64-row tiles, 2 CTAs/SM ======================
// hi-weights in SMEM; LO-WEIGHT FRAGMENTS IN REGISTERS (loaded once per CTA).
#define PAD 136
#define ATILE (64 * PAD * 2)               // 17408
#define WTILE (128 * PAD * 2)              // 34816
#define OFF_AHI 0
#define OFF_ALO ATILE
#define OFF_W1H (2 * ATILE)                // 34816
#define OFF_W2H (2 * ATILE + WTILE)        // 69632
#define SMEM_F  (2 * ATILE + 2 * WTILE)    // 104448 -> 2 CTAs/SM

template<int FINAL>
__global__ __launch_bounds__(256, 2)
void gemm_fused(const float* __restrict__ A,
                const __nv_bfloat16* __restrict__ W1h, const __nv_bfloat16* __restrict__ W1l,
                const __nv_bfloat16* __restrict__ W2h, const __nv_bfloat16* __restrict__ W2l,
                const float* __restrict__ b1, const float* __restrict__ b2,
                float* __restrict__ Cf, const int* __restrict__ batch,
                int M, int tiles) {
    extern __shared__ char smem[];
    uint32_t sb = smem_u32(smem);
    int t = threadIdx.x, wid = t >> 5, lane = t & 31;
    int warp_m = wid & 1, warp_n = wid >> 1;

    // lane addressing
    int a_r = warp_m * 32 + (lane & 15);
    int a_k = (lane >> 4) * 8;
    uint32_t aoff = (uint32_t)(a_r * PAD + a_k) * 2;
    int b_n = warp_n * 32 + (lane & 7) + ((lane >> 4) << 3);
    int b_k = ((lane >> 3) & 1) * 8;
    uint32_t boff = (uint32_t)(b_n * PAD + b_k) * 2;
    int g = lane >> 2, tq = lane & 3;

    // ---- stage 1: hi weights to homes + W1l to stage (A-tile area) ----
    #pragma unroll
    for (int i = 0; i < 8; i++) {
        int idx = i * 256 + t;
        int n = idx >> 4, k8 = idx & 15;
        uint32_t off = (uint32_t)(n * PAD + k8 * 8) * 2;
        CP_ASYNC16(sb + OFF_W1H + off, (const char*)W1h + idx * 16);
        CP_ASYNC16(sb + OFF_W2H + off, (const char*)W2h + idx * 16);
        CP_ASYNC16(sb + OFF_AHI + off, (const char*)W1l + idx * 16);
    }
    CP_COMMIT();
    CP_WAIT0();
    __syncthreads();

    uint32_t w1l[8][2][4];
    #pragma unroll
    for (int ks = 0; ks < 8; ks++)
        #pragma unroll
        for (int nb = 0; nb < 2; nb++) {
            uint32_t bd = sb + OFF_AHI + boff + (uint32_t)(nb * 16 * PAD) * 2 + ks * 32;
            LDSM_X4(w1l[ks][nb][0], w1l[ks][nb][1], w1l[ks][nb][2], w1l[ks][nb][3], bd);
        }
    __syncthreads();

    // ---- stage 2: W2l to stage ----
    #pragma unroll
    for (int i = 0; i < 8; i++) {
        int idx = i * 256 + t;
        int n = idx >> 4, k8 = idx & 15;
        uint32_t off = (uint32_t)(n * PAD + k8 * 8) * 2;
        CP_ASYNC16(sb + OFF_AHI + off, (const char*)W2l + idx * 16);
    }
    CP_COMMIT();
    CP_WAIT0();
    __syncthreads();

    uint32_t w2l[8][2][4];
    #pragma unroll
    for (int ks = 0; ks < 8; ks++)
        #pragma unroll
        for (int nb = 0; nb < 2; nb++) {
            uint32_t bd = sb + OFF_AHI + boff + (uint32_t)(nb * 16 * PAD) * 2 + ks * 32;
            LDSM_X4(w2l[ks][nb][0], w2l[ks][nb][1], w2l[ks][nb][2], w2l[ks][nb][3], bd);
        }

    for (int tile = blockIdx.x; tile < tiles; tile += gridDim.x) {
        int row0 = tile * 64;
        __syncthreads();                   // prior reads of A bufs (or w2l stage) done

        // ---- A: load f32, split bf16 hi/lo (64 rows) ----
        #pragma unroll
        for (int i = 0; i < 4; i++) {
            int idx = i * 256 + t;
            int r = idx >> 4, k8 = idx & 15;
            int row = row0 + r;
            if (row >= M) row = M - 1;
            const float4* ap = (const float4*)(A + (size_t)row * HID + k8 * 8);
            float4 aA = ap[0], aB = ap[1];
            __nv_bfloat162 h0 = __floats2bfloat162_rn(aA.x, aA.y);
            __nv_bfloat162 h1 = __floats2bfloat162_rn(aA.z, aA.w);
            __nv_bfloat162 h2 = __floats2bfloat162_rn(aB.x, aB.y);
            __nv_bfloat162 h3 = __floats2bfloat162_rn(aB.z, aB.w);
            __nv_bfloat162 l0 = __floats2bfloat162_rn(aA.x - __bfloat162float(h0.x), aA.y - __bfloat162float(h0.y));
            __nv_bfloat162 l1 = __floats2bfloat162_rn(aA.z - __bfloat162float(h1.x), aA.w - __bfloat162float(h1.y));
            __nv_bfloat162 l2 = __floats2bfloat162_rn(aB.x - __bfloat162float(h2.x), aB.y - __bfloat162float(h2.y));
            __nv_bfloat162 l3 = __floats2bfloat162_rn(aB.z - __bfloat162float(h3.x), aB.w - __bfloat162float(h3.y));
            uint4 hv = {*(uint32_t*)&h0, *(uint32_t*)&h1, *(uint32_t*)&h2, *(uint32_t*)&h3};
            uint4 lv = {*(uint32_t*)&l0, *(uint32_t*)&l1, *(uint32_t*)&l2, *(uint32_t*)&l3};
            uint32_t off = (uint32_t)(r * PAD + k8 * 8) * 2;
            *(uint4*)(smem + OFF_AHI + off) = hv;
            *(uint4*)(smem + OFF_ALO + off) = lv;
        }
        __syncthreads();

        float acc[2][4][4];

        // ---- mainloop 1: h @ W1 ----
        #pragma unroll
        for (int i = 0; i < 2; i++)
            #pragma unroll
            for (int j = 0; j < 4; j++)
                acc[i][j][0] = acc[i][j][1] = acc[i][j][2] = acc[i][j][3] = 0.f;

        #pragma unroll
        for (int ks = 0; ks < 8; ks++) {
            uint32_t kb = (uint32_t)(ks * 16) * 2;
            uint32_t ah[2][4], al[2][4], bh[2][4];
            #pragma unroll
            for (int mt = 0; mt < 2; mt++) {
                uint32_t ad = sb + aoff + (uint32_t)(mt * 16 * PAD) * 2 + kb;
                LDSM_X4(ah[mt][0], ah[mt][1], ah[mt][2], ah[mt][3], ad + OFF_AHI);
                LDSM_X4(al[mt][0], al[mt][1], al[mt][2], al[mt][3], ad + OFF_ALO);
            }
            #pragma unroll
            for (int nb = 0; nb < 2; nb++) {
                uint32_t bd = sb + OFF_W1H + boff + (uint32_t)(nb * 16 * PAD) * 2 + kb;
                LDSM_X4(bh[nb][0], bh[nb][1], bh[nb][2], bh[nb][3], bd);
            }
            #pragma unroll
            for (int mt = 0; mt < 2; mt++) {
                #pragma unroll
                for (int nt = 0; nt < 4; nt++) {
                    int nb = nt >> 1, h = (nt & 1) * 2;
                    MMA16816(acc[mt][nt], ah[mt], bh[nb][h], bh[nb][h + 1]);
                    MMA16816(acc[mt][nt], ah[mt], w1l[ks][nb][h], w1l[ks][nb][h + 1]);
                    MMA16816(acc[mt][nt], al[mt], bh[nb][h], bh[nb][h + 1]);
                }
            }
        }

        // ---- bias1 + relu + split -> overwrite A buffers as T ----
        __syncthreads();
        #pragma unroll
        for (int mt = 0; mt < 2; mt++) {
            int rloc = warp_m * 32 + mt * 16 + g;
            #pragma unroll
            for (int nt = 0; nt < 4; nt++) {
                int col = warp_n * 32 + nt * 8 + tq * 2;
                float bx = __ldg(b1 + col), by = __ldg(b1 + col + 1);
                float v0 = fmaxf(acc[mt][nt][0] + bx, 0.f);
                float v1 = fmaxf(acc[mt][nt][1] + by, 0.f);
                float v2 = fmaxf(acc[mt][nt][2] + bx, 0.f);
                float v3 = fmaxf(acc[mt][nt][3] + by, 0.f);
                __nv_bfloat162 hA = __floats2bfloat162_rn(v0, v1);
                __nv_bfloat162 lA = __floats2bfloat162_rn(v0 - __bfloat162float(hA.x),
                                                          v1 - __bfloat162float(hA.y));
                __nv_bfloat162 hB = __floats2bfloat162_rn(v2, v3);
                __nv_bfloat162 lB = __floats2bfloat162_rn(v2 - __bfloat162float(hB.x),
                                                          v3 - __bfloat162float(hB.y));
                uint32_t o0 = (uint32_t)(rloc * PAD + col) * 2;
                uint32_t o1 = (uint32_t)((rloc + 8) * PAD + col) * 2;
                *(uint32_t*)(smem + OFF_AHI + o0) = *(uint32_t*)&hA;
                *(uint32_t*)(smem + OFF_ALO + o0) = *(uint32_t*)&lA;
                *(uint32_t*)(smem + OFF_AHI + o1) = *(uint32_t*)&hB;
                *(uint32_t*)(smem + OFF_ALO + o1) = *(uint32_t*)&lB;
            }
        }
        __syncthreads();

        // ---- mainloop 2: T @ W2 ----
        #pragma unroll
        for (int i = 0; i < 2; i++)
            #pragma unroll
            for (int j = 0; j < 4; j++)
                acc[i][j][0] = acc[i][j][1] = acc[i][j][2] = acc[i][j][3] = 0.f;

        #pragma unroll
        for (int ks = 0; ks < 8; ks++) {
            uint32_t kb = (uint32_t)(ks * 16) * 2;
            uint32_t ah[2][4], al[2][4], bh[2][4];
            #pragma unroll
            for (int mt = 0; mt < 2; mt++) {
                uint32_t ad = sb + aoff + (uint32_t)(mt * 16 * PAD) * 2 + kb;
                LDSM_X4(ah[mt][0], ah[mt][1], ah[mt][2], ah[mt][3], ad + OFF_AHI);
                LDSM_X4(al[mt][0], al[mt][1], al[mt][2], al[mt][3], ad + OFF_ALO);
            }
            #pragma unroll
            for (int nb = 0; nb < 2; nb++) {
                uint32_t bd = sb + OFF_W2H + boff + (uint32_t)(nb * 16 * PAD) * 2 + kb;
                LDSM_X4(bh[nb][0], bh[nb][1], bh[nb][2], bh[nb][3], bd);
            }
            #pragma unroll
            for (int mt = 0; mt < 2; mt++) {
                #pragma unroll
                for (int nt = 0; nt < 4; nt++) {
                    int nb = nt >> 1, h = (nt & 1) * 2;
                    MMA16816(acc[mt][nt], ah[mt], bh[nb][h], bh[nb][h + 1]);
                    MMA16816(acc[mt][nt], ah[mt], w2l[ks][nb][h], w2l[ks][nb][h + 1]);
                    MMA16816(acc[mt][nt], al[mt], bh[nb][h], bh[nb][h + 1]);
                }
            }
        }

        // ---- epilogue ----
        #pragma unroll
        for (int mt = 0; mt < 2; mt++) {
            int rbase = row0 + warp_m * 32 + mt * 16 + g;
            #pragma unroll
            for (int nt = 0; nt < 4; nt++) {
                int col = warp_n * 32 + nt * 8 + tq * 2;
                float bx = __ldg(b2 + col), by = __ldg(b2 + col + 1);
                float v0 = acc[mt][nt][0] + bx, v1 = acc[mt][nt][1] + by;
                float v2 = acc[mt][nt][2] + bx, v3 = acc[mt][nt][3] + by;
                if (FINAL == 0) {
                    v0 = fmaxf(v0, 0.f); v1 = fmaxf(v1, 0.f);
                    v2 = fmaxf(v2, 0.f); v3 = fmaxf(v3, 0.f);
                    if (rbase < M)
                        *(float2*)(Cf + (size_t)rbase * HID + col) = make_float2(v0, v1);
                    if (rbase + 8 < M)
                        *(float2*)(Cf + (size_t)(rbase + 8) * HID + col) = make_float2(v2, v3);
                } else {
                    if (rbase < M)
                        red_add_v2(g_pool + __ldg(batch + rbase) * HID + col, v0, v1);
                    if (rbase + 8 < M)
                        red_add_v2(g_pool + __ldg(batch + rbase + 8) * HID + col, v2, v3);
                }
            }
        }
    }
}

// ---------------- heads ---------------------------------------------------------
__global__ void heads_kernel(const float* __restrict__ W1, const float* __restrict__ b1,
                             const float* __restrict__ W2, const float* __restrict__ b2,
                             float* __restrict__ out) {
    __shared__ float sa[HID];
    __shared__ float red[HID];
    __shared__ float o[4];
    int g = blockIdx.x, j = threadIdx.x;
    sa[j] = g_pool[g * HID + j];
    __syncthreads();
    for (int k = 0; k < 4; k++) {
        float acc = b1[k * HID + j];
        const float* w = W1 + k * HID * HID + j;
        #pragma unroll 8
        for (int i = 0; i < HID; i++) acc += sa[i] * w[i * HID];
        acc = fmaxf(acc, 0.f);
        red[j] = acc * W2[k * HID + j];
        __syncthreads();
        for (int s = 64; s > 0; s >>= 1) {
            if (j < s) red[j] += red[j + s];
            __syncthreads();
        }
        if (j == 0) o[k] = red[0] + b2[k];
        __syncthreads();
    }
    if (j == 0) {
        float alpha = fmaxf(softplusf(o[0]) + 1.f, 1.f + 1e-4f);
        float beta  = softplusf(o[1]);
        float nu    = softplusf(o[2]);
        float gamma = o[3];
        float am1 = alpha - 1.f;
        out[g]            = gamma;
        out[NG + g]       = beta / am1;
        out[2 * NG + g]   = beta / (am1 * nu);
        out[3 * NG + g]   = nu;
        out[4 * NG + g]   = alpha;
        out[5 * NG + g]   = beta;
    }
}

// ---------------- driver --------------------------------------------------------
extern "C" void kernel_launch(void* const* d_in, const int* in_sizes, int n_in,
                              void* d_out, int out_size) {
    const int*   z        = (const int*)d_in[0];
    const float* pos      = (const float*)d_in[1];
    const int*   batch    = (const int*)d_in[2];
    const int*   eidx     = (const int*)d_in[3];
    const float* embed    = (const float*)d_in[4];
    const float* W_pos    = (const float*)d_in[5];
    const float* b_pos    = (const float*)d_in[6];
    const float* W_comb   = (const float*)d_in[7];
    const float* b_comb   = (const float*)d_in[8];
    const float* gin_W1   = (const float*)d_in[9];
    const float* gin_b1   = (const float*)d_in[10];
    const float* gin_W2   = (const float*)d_in[11];
    const float* gin_b2   = (const float*)d_in[12];
    const float* head_W1  = (const float*)d_in[13];
    const float* head_b1  = (const float*)d_in[14];
    const float* head_W2  = (const float*)d_in[15];
    const float* head_b2  = (const float*)d_in[16];
    float* out = (float*)d_out;

    const int N = in_sizes[0];
    const int E = in_sizes[3] / 2;
    const int* src = eidx;
    const int* dst = eidx + E;

    float *x, *h;
    __nv_bfloat16 *whi, *wlo;
    cudaGetSymbolAddress((void**)&x, g_x);
    cudaGetSymbolAddress((void**)&h, g_h);
    cudaGetSymbolAddress((void**)&whi, g_whi);
    cudaGetSymbolAddress((void**)&wlo, g_wlo);

    cudaFuncSetAttribute(gemm_fused<0>, cudaFuncAttributeMaxDynamicSharedMemorySize, SMEM_F);
    cudaFuncSetAttribute(gemm_fused<1>, cudaFuncAttributeMaxDynamicSharedMemorySize, SMEM_F);

    // 1. zeros + CSR build + weight prep + x0 (R10 setup chain)
    const int zmax = (NG * HID > NN) ? NG * HID : NN;
    zero_kernel<<<(zmax + 255) / 256, 256>>>();
    hist_kernel<<<((E + 3) / 4 + 255) / 256, 256>>>(dst, E);
    scan_kernel<<<1, 1024>>>();
    fill_kernel<<<((E + 3) / 4 + 255) / 256, 256>>>(src, dst, E);
    prep_kernel<<<109, 128>>>(embed, W_pos, b_pos, W_comb, b_comb, gin_W1, gin_W2);
    x0_kernel<<<(N * 32 + 255) / 256, 256>>>(z, pos, N);

    // 2. GIN layers (agg + persistent fused MLP, 64-row tiles 2 CTAs/SM)
    const int tiles = (N + 63) / 64;
    const int pblocks = (tiles < 296) ? tiles : 296;
    const int agg_blocks = (N * 32 + 255) / 256;
    for (int l = 0; l < 4; l++) {
        agg_kernel<<<agg_blocks, 256>>>(N);
        const __nv_bfloat16* w1h = whi + (size_t)(2 * l) * HID * HID;
        const __nv_bfloat16* w1l = wlo + (size_t)(2 * l) * HID * HID;
        const __nv_bfloat16* w2h = whi + (size_t)(2 * l + 1) * HID * HID;
        const __nv_bfloat16* w2l = wlo + (size_t)(2 * l + 1) * HID * HID;
        if (l < 3)
            gemm_fused<0><<<pblocks, 256, SMEM_F>>>(h, w1h, w1l, w2h, w2l,
                                                    gin_b1 + l * HID, gin_b2 + l * HID,
                                                    x, nullptr, N, tiles);
        else
            gemm_fused<1><<<pblocks, 256, SMEM_F>>>(h, w1h, w1l, w2h, w2l,
                                                    gin_b1 + l * HID, gin_b2 + l * HID,
                                                    nullptr, batch, N, tiles);
    }

    // 3. heads
    heads_kernel<<<NG, 128>>>(head_W1, head_b1, head_W2, head_b2, out);
}

// round 16
// speedup vs baseline: 1.1123x; 1.0890x over previous
#include <cuda_runtime.h>
#include <cuda_bf16.h>
#include <math.h>
#include <stdint.h>

#define NN 50000
#define NE_MAX 800000
#define HID 128
#define NG 512

// ---------------- scratch (static __device__, no runtime alloc) ----------------
__device__ float g_x[NN * HID];
__device__ float g_h[NN * HID];
__device__ float g_pool[NG * HID];
__device__ float g_EW[100 * HID];
__device__ float g_Wpc[4 * HID];
__device__ int   g_deg[NN];
__device__ int   g_off[NN + 1];
__device__ int   g_cur[NN];
__device__ int   g_srcs[NE_MAX];
__device__ __nv_bfloat16 g_whi[8 * HID * HID];
__device__ __nv_bfloat16 g_wlo[8 * HID * HID];

__device__ __forceinline__ float softplusf(float x) {
    return fmaxf(x, 0.f) + log1pf(expf(-fabsf(x)));
}

__device__ __forceinline__ void red_add_v2(float* p, float a, float b) {
    asm volatile("red.global.add.v2.f32 [%0], {%1, %2};"
                 :: "l"(p), "f"(a), "f"(b) : "memory");
}

__device__ __forceinline__ uint32_t smem_u32(const void* p) {
    uint32_t a;
    asm("{ .reg .u64 t; cvta.to.shared.u64 t, %1; cvt.u32.u64 %0, t; }" : "=r"(a) : "l"(p));
    return a;
}

#define LDSM_X4(r0, r1, r2, r3, addr) \
    asm volatile("ldmatrix.sync.aligned.m8n8.x4.shared.b16 {%0,%1,%2,%3}, [%4];" \
                 : "=r"(r0), "=r"(r1), "=r"(r2), "=r"(r3) : "r"(addr))

#define MMA16816(c, a, b0, b1) \
    asm volatile("mma.sync.aligned.m16n8k16.row.col.f32.bf16.bf16.f32 " \
                 "{%0,%1,%2,%3}, {%4,%5,%6,%7}, {%8,%9}, {%0,%1,%2,%3};" \
                 : "+f"((c)[0]), "+f"((c)[1]), "+f"((c)[2]), "+f"((c)[3]) \
                 : "r"((a)[0]), "r"((a)[1]), "r"((a)[2]), "r"((a)[3]), "r"(b0), "r"(b1))

#define CP_ASYNC16(dst, src) \
    asm volatile("cp.async.ca.shared.global [%0], [%1], 16;" :: "r"(dst), "l"(src))
#define CP_COMMIT() asm volatile("cp.async.commit_group;" ::: "memory")
#define CP_WAIT0()  asm volatile("cp.async.wait_group 0;" ::: "memory")

// ================= CSR build ====================================================
__global__ void hist_kernel(const int* __restrict__ dst, int E) {
    int i = blockIdx.x * blockDim.x + threadIdx.x;
    int e = i * 4;
    if (e + 3 < E) {
        int4 d = ((const int4*)dst)[i];
        atomicAdd(&g_deg[d.x], 1);
        atomicAdd(&g_deg[d.y], 1);
        atomicAdd(&g_deg[d.z], 1);
        atomicAdd(&g_deg[d.w], 1);
    } else {
        for (; e < E; e++) atomicAdd(&g_deg[__ldg(dst + e)], 1);
    }
}

__global__ void scan_kernel() {
    __shared__ int part[1024];
    int t = threadIdx.x;
    const int CH = (NN + 1023) / 1024;
    int base = t * CH;
    int s = 0;
    #pragma unroll 8
    for (int i = 0; i < CH; i++) { int idx = base + i; if (idx < NN) s += g_deg[idx]; }
    part[t] = s;
    __syncthreads();
    for (int off = 1; off < 1024; off <<= 1) {
        int v = (t >= off) ? part[t - off] : 0;
        __syncthreads();
        part[t] += v;
        __syncthreads();
    }
    int run = (t == 0) ? 0 : part[t - 1];
    #pragma unroll 8
    for (int i = 0; i < CH; i++) {
        int idx = base + i;
        if (idx < NN) { g_off[idx] = run; g_cur[idx] = run; run += g_deg[idx]; }
    }
    if (t == 1023) g_off[NN] = run;
}

__global__ void fill_kernel(const int* __restrict__ src, const int* __restrict__ dst, int E) {
    int i = blockIdx.x * blockDim.x + threadIdx.x;
    int e = i * 4;
    if (e + 3 < E) {
        int4 s = ((const int4*)src)[i];
        int4 d = ((const int4*)dst)[i];
        int p0 = atomicAdd(&g_cur[d.x], 1);
        int p1 = atomicAdd(&g_cur[d.y], 1);
        int p2 = atomicAdd(&g_cur[d.z], 1);
        int p3 = atomicAdd(&g_cur[d.w], 1);
        g_srcs[p0] = s.x;
        g_srcs[p1] = s.y;
        g_srcs[p2] = s.z;
        g_srcs[p3] = s.w;
    } else {
        for (; e < E; e++) {
            int p = atomicAdd(&g_cur[__ldg(dst + e)], 1);
            g_srcs[p] = __ldg(src + e);
        }
    }
}

// ---------------- merged zero + prep (R12-verified merge) ----------------------
// blocks [0,256): zero deg+pool. blocks [256,365): embedding fold + W split.
__global__ void zero_prep_kernel(const float* __restrict__ embed_tab,
                                 const float* __restrict__ W_pos,
                                 const float* __restrict__ b_pos,
                                 const float* __restrict__ W_comb,
                                 const float* __restrict__ b_comb,
                                 const float* __restrict__ W1all,
                                 const float* __restrict__ W2all) {
    int blk = blockIdx.x;
    if (blk < 256) {
        int i = blk * 256 + threadIdx.x;
        if (i < NN) g_deg[i] = 0;
        if (i < NG * HID) g_pool[i] = 0.f;
        return;
    }
    if (threadIdx.x >= 128) return;
    int b = blk - 256;                 // 0..108
    int j = threadIdx.x;
    if (b < 100) {
        float acc = 0.f;
        #pragma unroll 8
        for (int i = 0; i < HID; i++)
            acc += embed_tab[b * HID + i] * W_comb[i * HID + j];
        g_EW[b * HID + j] = acc;
    } else if (b == 100) {
        float a0 = 0.f, a1 = 0.f, a2 = 0.f, ab = 0.f;
        #pragma unroll 8
        for (int i = 0; i < HID; i++) {
            float w = W_comb[(HID + i) * HID + j];
            a0 += W_pos[i] * w;
            a1 += W_pos[HID + i] * w;
            a2 += W_pos[2 * HID + i] * w;
            ab += b_pos[i] * w;
        }
        g_Wpc[j]           = a0;
        g_Wpc[HID + j]     = a1;
        g_Wpc[2 * HID + j] = a2;
        g_Wpc[3 * HID + j] = ab + b_comb[j];
    } else {
        int mat = b - 101;
        const float* W = ((mat & 1) ? W2all : W1all) + (size_t)(mat >> 1) * HID * HID;
        __nv_bfloat16* hi = g_whi + (size_t)mat * HID * HID;
        __nv_bfloat16* lo = g_wlo + (size_t)mat * HID * HID;
        #pragma unroll 4
        for (int k = 0; k < HID; k++) {
            float w = W[k * HID + j];
            __nv_bfloat16 hh = __float2bfloat16(w);
            hi[j * HID + k] = hh;
            lo[j * HID + k] = __float2bfloat16(w - __bfloat162float(hh));
        }
    }
}

// ---------------- x0 = relu(EW[z] + pos@Wpc + bfuse) ---------------------------
__global__ void x0_kernel(const int* __restrict__ z, const float* __restrict__ pos, int N) {
    int tid = blockIdx.x * blockDim.x + threadIdx.x;
    int n = tid >> 5;
    if (n >= N) return;
    int c = tid & 31;
    int zz = __ldg(z + n);
    float p0 = __ldg(pos + n * 3), p1 = __ldg(pos + n * 3 + 1), p2 = __ldg(pos + n * 3 + 2);
    float4 ew = *(const float4*)(g_EW + zz * HID + c * 4);
    float4 w0 = *(const float4*)(g_Wpc + c * 4);
    float4 w1 = *(const float4*)(g_Wpc + HID + c * 4);
    float4 w2 = *(const float4*)(g_Wpc + 2 * HID + c * 4);
    float4 bf = *(const float4*)(g_Wpc + 3 * HID + c * 4);
    float4 v;
    v.x = fmaxf(ew.x + p0 * w0.x + p1 * w1.x + p2 * w2.x + bf.x, 0.f);
    v.y = fmaxf(ew.y + p0 * w0.y + p1 * w1.y + p2 * w2.y + bf.y, 0.f);
    v.z = fmaxf(ew.z + p0 * w0.z + p1 * w1.z + p2 * w2.z + bf.z, 0.f);
    v.w = fmaxf(ew.w + p0 * w0.w + p1 * w1.w + p2 * w2.w + bf.w, 0.f);
    *(float4*)(g_x + n * HID + c * 4) = v;
}

// ---------------- CSR aggregation (fp32, 8-deep unroll) ------------------------
__global__ void agg_kernel(int N) {
    int tid = blockIdx.x * blockDim.x + threadIdx.x;
    int n = tid >> 5;
    if (n >= N) return;
    int lane = tid & 31;
    const float4* x4 = (const float4*)g_x;
    float4 a0 = x4[n * 32 + lane];
    float4 a1 = {0.f, 0.f, 0.f, 0.f};
    float4 a2 = {0.f, 0.f, 0.f, 0.f};
    float4 a3 = {0.f, 0.f, 0.f, 0.f};
    int beg = __ldg(&g_off[n]), end = __ldg(&g_off[n + 1]);
    int e = beg;
    for (; e + 8 <= end; e += 8) {
        int s0 = __ldg(&g_srcs[e]);
        int s1 = __ldg(&g_srcs[e + 1]);
        int s2 = __ldg(&g_srcs[e + 2]);
        int s3 = __ldg(&g_srcs[e + 3]);
        int s4 = __ldg(&g_srcs[e + 4]);
        int s5 = __ldg(&g_srcs[e + 5]);
        int s6 = __ldg(&g_srcs[e + 6]);
        int s7 = __ldg(&g_srcs[e + 7]);
        float4 v0 = x4[s0 * 32 + lane];
        float4 v1 = x4[s1 * 32 + lane];
        float4 v2 = x4[s2 * 32 + lane];
        float4 v3 = x4[s3 * 32 + lane];
        float4 v4 = x4[s4 * 32 + lane];
        float4 v5 = x4[s5 * 32 + lane];
        float4 v6 = x4[s6 * 32 + lane];
        float4 v7 = x4[s7 * 32 + lane];
        a0.x += v0.x; a0.y += v0.y; a0.z += v0.z; a0.w += v0.w;
        a1.x += v1.x; a1.y += v1.y; a1.z += v1.z; a1.w += v1.w;
        a2.x += v2.x; a2.y += v2.y; a2.z += v2.z; a2.w += v2.w;
        a3.x += v3.x; a3.y += v3.y; a3.z += v3.z; a3.w += v3.w;
        a0.x += v4.x; a0.y += v4.y; a0.z += v4.z; a0.w += v4.w;
        a1.x += v5.x; a1.y += v5.y; a1.z += v5.z; a1.w += v5.w;
        a2.x += v6.x; a2.y += v6.y; a2.z += v6.z; a2.w += v6.w;
        a3.x += v7.x; a3.y += v7.y; a3.z += v7.z; a3.w += v7.w;
    }
    for (; e < end; e++) {
        int s = __ldg(&g_srcs[e]);
        float4 v = x4[s * 32 + lane];
        a0.x += v.x; a0.y += v.y; a0.z += v.z; a0.w += v.w;
    }
    float4 r;
    r.x = a0.x + a1.x + a2.x + a3.x;
    r.y = a0.y + a1.y + a2.y + a3.y;
    r.z = a0.z + a1.z + a2.z + a3.z;
    r.w = a0.w + a1.w + a2.w + a3.w;
    ((float4*)g_h)[n * 32 + lane] = r;
}

// ========== PERSISTENT fused MLP (R10 champion config: 128-row, 1 CTA/SM) ======
#define PAD 136
#define TILE (128 * PAD * 2)
#define OFF_AHI 0
#define OFF_ALO TILE
#define OFF_W1H (2 * TILE)
#define OFF_W1L (3 * TILE)
#define OFF_W2H (4 * TILE)
#define OFF_W2L (5 * TILE)
#define SMEM_F  (6 * TILE)

template<int FINAL>
__global__ __launch_bounds__(256, 1)
void gemm_fused(const float* __restrict__ A,
                const __nv_bfloat16* __restrict__ W1h, const __nv_bfloat16* __restrict__ W1l,
                const __nv_bfloat16* __restrict__ W2h, const __nv_bfloat16* __restrict__ W2l,
                const float* __restrict__ b1, const float* __restrict__ b2,
                float* __restrict__ Cf, const int* __restrict__ batch,
                int M, int tiles) {
    extern __shared__ char smem[];
    uint32_t sb = smem_u32(smem);
    int t = threadIdx.x, wid = t >> 5, lane = t & 31;
    int warp_m = wid & 1, warp_n = wid >> 1;

    #pragma unroll
    for (int i = 0; i < 8; i++) {
        int idx = i * 256 + t;
        int n = idx >> 4, k8 = idx & 15;
        uint32_t off = (uint32_t)(n * PAD + k8 * 8) * 2;
        CP_ASYNC16(sb + OFF_W1H + off, (const char*)W1h + idx * 16);
        CP_ASYNC16(sb + OFF_W1L + off, (const char*)W1l + idx * 16);
        CP_ASYNC16(sb + OFF_W2H + off, (const char*)W2h + idx * 16);
        CP_ASYNC16(sb + OFF_W2L + off, (const char*)W2l + idx * 16);
    }
    CP_COMMIT();

    int a_r = warp_m * 64 + (lane & 15);
    int a_k = (lane >> 4) * 8;
    uint32_t aoff = (uint32_t)(a_r * PAD + a_k) * 2;
    int b_n = warp_n * 32 + (lane & 7) + ((lane >> 4) << 3);
    int b_k = ((lane >> 3) & 1) * 8;
    uint32_t boff = (uint32_t)(b_n * PAD + b_k) * 2;
    int g = lane >> 2, tq = lane & 3;

    bool first = true;

    for (int tile = blockIdx.x; tile < tiles; tile += gridDim.x) {
        int row0 = tile * 128;
        __syncthreads();

        #pragma unroll
        for (int i = 0; i < 8; i++) {
            int idx = i * 256 + t;
            int r = idx >> 4, k8 = idx & 15;
            int row = row0 + r;
            if (row >= M) row = M - 1;
            const float4* ap = (const float4*)(A + (size_t)row * HID + k8 * 8);
            float4 aA = ap[0], aB = ap[1];
            __nv_bfloat162 h0 = __floats2bfloat162_rn(aA.x, aA.y);
            __nv_bfloat162 h1 = __floats2bfloat162_rn(aA.z, aA.w);
            __nv_bfloat162 h2 = __floats2bfloat162_rn(aB.x, aB.y);
            __nv_bfloat162 h3 = __floats2bfloat162_rn(aB.z, aB.w);
            __nv_bfloat162 l0 = __floats2bfloat162_rn(aA.x - __bfloat162float(h0.x), aA.y - __bfloat162float(h0.y));
            __nv_bfloat162 l1 = __floats2bfloat162_rn(aA.z - __bfloat162float(h1.x), aA.w - __bfloat162float(h1.y));
            __nv_bfloat162 l2 = __floats2bfloat162_rn(aB.x - __bfloat162float(h2.x), aB.y - __bfloat162float(h2.y));
            __nv_bfloat162 l3 = __floats2bfloat162_rn(aB.z - __bfloat162float(h3.x), aB.w - __bfloat162float(h3.y));
            uint4 hv = {*(uint32_t*)&h0, *(uint32_t*)&h1, *(uint32_t*)&h2, *(uint32_t*)&h3};
            uint4 lv = {*(uint32_t*)&l0, *(uint32_t*)&l1, *(uint32_t*)&l2, *(uint32_t*)&l3};
            uint32_t off = (uint32_t)(r * PAD + k8 * 8) * 2;
            *(uint4*)(smem + OFF_AHI + off) = hv;
            *(uint4*)(smem + OFF_ALO + off) = lv;
        }
        if (first) { CP_WAIT0(); first = false; }
        __syncthreads();

        float acc[4][4][4];

        // ---- mainloop 1: h @ W1 ----
        #pragma unroll
        for (int i = 0; i < 4; i++)
            #pragma unroll
            for (int j = 0; j < 4; j++)
                acc[i][j][0] = acc[i][j][1] = acc[i][j][2] = acc[i][j][3] = 0.f;

        #pragma unroll
        for (int ks = 0; ks < 8; ks++) {
            uint32_t kb = (uint32_t)(ks * 16) * 2;
            uint32_t ah[4][4], al[4][4], bh[2][4], bl[2][4];
            #pragma unroll
            for (int mt = 0; mt < 4; mt++) {
                uint32_t ad = sb + aoff + (uint32_t)(mt * 16 * PAD) * 2 + kb;
                LDSM_X4(ah[mt][0], ah[mt][1], ah[mt][2], ah[mt][3], ad + OFF_AHI);
                LDSM_X4(al[mt][0], al[mt][1], al[mt][2], al[mt][3], ad + OFF_ALO);
            }
            #pragma unroll
            for (int nb = 0; nb < 2; nb++) {
                uint32_t bd = sb + boff + (uint32_t)(nb * 16 * PAD) * 2 + kb;
                LDSM_X4(bh[nb][0], bh[nb][1], bh[nb][2], bh[nb][3], bd + OFF_W1H);
                LDSM_X4(bl[nb][0], bl[nb][1], bl[nb][2], bl[nb][3], bd + OFF_W1L);
            }
            #pragma unroll
            for (int mt = 0; mt < 4; mt++) {
                #pragma unroll
                for (int nt = 0; nt < 4; nt++) {
                    int nb = nt >> 1, h = (nt & 1) * 2;
                    MMA16816(acc[mt][nt], ah[mt], bh[nb][h], bh[nb][h + 1]);
                    MMA16816(acc[mt][nt], ah[mt], bl[nb][h], bl[nb][h + 1]);
                    MMA16816(acc[mt][nt], al[mt], bh[nb][h], bh[nb][h + 1]);
                }
            }
        }

        // ---- bias1 + relu + split -> overwrite A buffers as T ----
        __syncthreads();
        #pragma unroll
        for (int mt = 0; mt < 4; mt++) {
            int rloc = warp_m * 64 + mt * 16 + g;
            #pragma unroll
            for (int nt = 0; nt < 4; nt++) {
                int col = warp_n * 32 + nt * 8 + tq * 2;
                float bx = __ldg(b1 + col), by = __ldg(b1 + col + 1);
                float v0 = fmaxf(acc[mt][nt][0] + bx, 0.f);
                float v1 = fmaxf(acc[mt][nt][1] + by, 0.f);
                float v2 = fmaxf(acc[mt][nt][2] + bx, 0.f);
                float v3 = fmaxf(acc[mt][nt][3] + by, 0.f);
                __nv_bfloat162 hA = __floats2bfloat162_rn(v0, v1);
                __nv_bfloat162 lA = __floats2bfloat162_rn(v0 - __bfloat162float(hA.x),
                                                          v1 - __bfloat162float(hA.y));
                __nv_bfloat162 hB = __floats2bfloat162_rn(v2, v3);
                __nv_bfloat162 lB = __floats2bfloat162_rn(v2 - __bfloat162float(hB.x),
                                                          v3 - __bfloat162float(hB.y));
                uint32_t o0 = (uint32_t)(rloc * PAD + col) * 2;
                uint32_t o1 = (uint32_t)((rloc + 8) * PAD + col) * 2;
                *(uint32_t*)(smem + OFF_AHI + o0) = *(uint32_t*)&hA;
                *(uint32_t*)(smem + OFF_ALO + o0) = *(uint32_t*)&lA;
                *(uint32_t*)(smem + OFF_AHI + o1) = *(uint32_t*)&hB;
                *(uint32_t*)(smem + OFF_ALO + o1) = *(uint32_t*)&lB;
            }
        }
        __syncthreads();

        // ---- mainloop 2: T @ W2 ----
        #pragma unroll
        for (int i = 0; i < 4; i++)
            #pragma unroll
            for (int j = 0; j < 4; j++)
                acc[i][j][0] = acc[i][j][1] = acc[i][j][2] = acc[i][j][3] = 0.f;

        #pragma unroll
        for (int ks = 0; ks < 8; ks++) {
            uint32_t kb = (uint32_t)(ks * 16) * 2;
            uint32_t ah[4][4], al[4][4], bh[2][4], bl[2][4];
            #pragma unroll
            for (int mt = 0; mt < 4; mt++) {
                uint32_t ad = sb + aoff + (uint32_t)(mt * 16 * PAD) * 2 + kb;
                LDSM_X4(ah[mt][0], ah[mt][1], ah[mt][2], ah[mt][3], ad + OFF_AHI);
                LDSM_X4(al[mt][0], al[mt][1], al[mt][2], al[mt][3], ad + OFF_ALO);
            }
            #pragma unroll
            for (int nb = 0; nb < 2; nb++) {
                uint32_t bd = sb + boff + (uint32_t)(nb * 16 * PAD) * 2 + kb;
                LDSM_X4(bh[nb][0], bh[nb][1], bh[nb][2], bh[nb][3], bd + OFF_W2H);
                LDSM_X4(bl[nb][0], bl[nb][1], bl[nb][2], bl[nb][3], bd + OFF_W2L);
            }
            #pragma unroll
            for (int mt = 0; mt < 4; mt++) {
                #pragma unroll
                for (int nt = 0; nt < 4; nt++) {
                    int nb = nt >> 1, h = (nt & 1) * 2;
                    MMA16816(acc[mt][nt], ah[mt], bh[nb][h], bh[nb][h + 1]);
                    MMA16816(acc[mt][nt], ah[mt], bl[nb][h], bl[nb][h + 1]);
                    MMA16816(acc[mt][nt], al[mt], bh[nb][h], bh[nb][h + 1]);
                }
            }
        }

        // ---- epilogue ----
        #pragma unroll
        for (int mt = 0; mt < 4; mt++) {
            int rbase = row0 + warp_m * 64 + mt * 16 + g;
            #pragma unroll
            for (int nt = 0; nt < 4; nt++) {
                int col = warp_n * 32 + nt * 8 + tq * 2;
                float bx = __ldg(b2 + col), by = __ldg(b2 + col + 1);
                float v0 = acc[mt][nt][0] + bx, v1 = acc[mt][nt][1] + by;
                float v2 = acc[mt][nt][2] + bx, v3 = acc[mt][nt][3] + by;
                if (FINAL == 0) {
                    v0 = fmaxf(v0, 0.f); v1 = fmaxf(v1, 0.f);
                    v2 = fmaxf(v2, 0.f); v3 = fmaxf(v3, 0.f);
                    if (rbase < M)
                        *(float2*)(Cf + (size_t)rbase * HID + col) = make_float2(v0, v1);
                    if (rbase + 8 < M)
                        *(float2*)(Cf + (size_t)(rbase + 8) * HID + col) = make_float2(v2, v3);
                } else {
                    if (rbase < M)
                        red_add_v2(g_pool + __ldg(batch + rbase) * HID + col, v0, v1);
                    if (rbase + 8 < M)
                        red_add_v2(g_pool + __ldg(batch + rbase + 8) * HID + col, v2, v3);
                }
            }
        }
    }
}

// ---------------- heads ---------------------------------------------------------
__global__ void heads_kernel(const float* __restrict__ W1, const float* __restrict__ b1,
                             const float* __restrict__ W2, const float* __restrict__ b2,
                             float* __restrict__ out) {
    __shared__ float sa[HID];
    __shared__ float red[HID];
    __shared__ float o[4];
    int g = blockIdx.x, j = threadIdx.x;
    sa[j] = g_pool[g * HID + j];
    __syncthreads();
    for (int k = 0; k < 4; k++) {
        float acc = b1[k * HID + j];
        const float* w = W1 + k * HID * HID + j;
        #pragma unroll 8
        for (int i = 0; i < HID; i++) acc += sa[i] * w[i * HID];
        acc = fmaxf(acc, 0.f);
        red[j] = acc * W2[k * HID + j];
        __syncthreads();
        for (int s = 64; s > 0; s >>= 1) {
            if (j < s) red[j] += red[j + s];
            __syncthreads();
        }
        if (j == 0) o[k] = red[0] + b2[k];
        __syncthreads();
    }
    if (j == 0) {
        float alpha = fmaxf(softplusf(o[0]) + 1.f, 1.f + 1e-4f);
        float beta  = softplusf(o[1]);
        float nu    = softplusf(o[2]);
        float gamma = o[3];
        float am1 = alpha - 1.f;
        out[g]            = gamma;
        out[NG + g]       = beta / am1;
        out[2 * NG + g]   = beta / (am1 * nu);
        out[3 * NG + g]   = nu;
        out[4 * NG + g]   = alpha;
        out[5 * NG + g]   = beta;
    }
}

// ---------------- driver --------------------------------------------------------
extern "C" void kernel_launch(void* const* d_in, const int* in_sizes, int n_in,
                              void* d_out, int out_size) {
    const int*   z        = (const int*)d_in[0];
    const float* pos      = (const float*)d_in[1];
    const int*   batch    = (const int*)d_in[2];
    const int*   eidx     = (const int*)d_in[3];
    const float* embed    = (const float*)d_in[4];
    const float* W_pos    = (const float*)d_in[5];
    const float* b_pos    = (const float*)d_in[6];
    const float* W_comb   = (const float*)d_in[7];
    const float* b_comb   = (const float*)d_in[8];
    const float* gin_W1   = (const float*)d_in[9];
    const float* gin_b1   = (const float*)d_in[10];
    const float* gin_W2   = (const float*)d_in[11];
    const float* gin_b2   = (const float*)d_in[12];
    const float* head_W1  = (const float*)d_in[13];
    const float* head_b1  = (const float*)d_in[14];
    const float* head_W2  = (const float*)d_in[15];
    const float* head_b2  = (const float*)d_in[16];
    float* out = (float*)d_out;

    const int N = in_sizes[0];
    const int E = in_sizes[3] / 2;
    const int* src = eidx;
    const int* dst = eidx + E;

    float *x, *h;
    __nv_bfloat16 *whi, *wlo;
    cudaGetSymbolAddress((void**)&x, g_x);
    cudaGetSymbolAddress((void**)&h, g_h);
    cudaGetSymbolAddress((void**)&whi, g_whi);
    cudaGetSymbolAddress((void**)&wlo, g_wlo);

    cudaFuncSetAttribute(gemm_fused<0>, cudaFuncAttributeMaxDynamicSharedMemorySize, SMEM_F);
    cudaFuncSetAttribute(gemm_fused<1>, cudaFuncAttributeMaxDynamicSharedMemorySize, SMEM_F);

    // 1. merged zero+prep; CSR build; x0 (R10 chain, one launch fewer)
    zero_prep_kernel<<<365, 256>>>(embed, W_pos, b_pos, W_comb, b_comb, gin_W1, gin_W2);
    hist_kernel<<<((E + 3) / 4 + 255) / 256, 256>>>(dst, E);
    scan_kernel<<<1, 1024>>>();
    fill_kernel<<<((E + 3) / 4 + 255) / 256, 256>>>(src, dst, E);
    x0_kernel<<<(N * 32 + 255) / 256, 256>>>(z, pos, N);

    // 2. GIN layers (agg + persistent fused MLP, R10 config)
    const int tiles = (N + 127) / 128;
    const int pblocks = (tiles < 148) ? tiles : 148;
    const int agg_blocks = (N * 32 + 255) / 256;
    for (int l = 0; l < 4; l++) {
        agg_kernel<<<agg_blocks, 256>>>(N);
        const __nv_bfloat16* w1h = whi + (size_t)(2 * l) * HID * HID;
        const __nv_bfloat16* w1l = wlo + (size_t)(2 * l) * HID * HID;
        const __nv_bfloat16* w2h = whi + (size_t)(2 * l + 1) * HID * HID;
        const __nv_bfloat16* w2l = wlo + (size_t)(2 * l + 1) * HID * HID;
        if (l < 3)
            gemm_fused<0><<<pblocks, 256, SMEM_F>>>(h, w1h, w1l, w2h, w2l,
                                                    gin_b1 + l * HID, gin_b2 + l * HID,
                                                    x, nullptr, N, tiles);
        else
            gemm_fused<1><<<pblocks, 256, SMEM_F>>>(h, w1h, w1l, w2h, w2l,
                                                    gin_b1 + l * HID, gin_b2 + l * HID,
                                                    nullptr, batch, N, tiles);
    }

    // 3. heads
    heads_kernel<<<NG, 128>>>(head_W1, head_b1, head_W2, head_b2, out);
}

// round 17
// speedup vs baseline: 1.1380x; 1.0231x over previous
#include <cuda_runtime.h>
#include <cuda_bf16.h>
#include <math.h>
#include <stdint.h>

#define NN 50000
#define NE_MAX 800000
#define HID 128
#define NG 512

// ---------------- scratch (static __device__, no runtime alloc) ----------------
__device__ float g_x[NN * HID];
__device__ float g_h[NN * HID];
__device__ float g_pool[NG * HID];
__device__ float g_EW[100 * HID];
__device__ float g_Wpc[4 * HID];
__device__ int   g_deg[NN];
__device__ int   g_off[NN + 1];
__device__ int   g_cur[NN];
__device__ int   g_srcs[NE_MAX];
__device__ __nv_bfloat16 g_whi[8 * HID * HID];
__device__ __nv_bfloat16 g_wlo[8 * HID * HID];

__device__ __forceinline__ float softplusf(float x) {
    return fmaxf(x, 0.f) + log1pf(expf(-fabsf(x)));
}

__device__ __forceinline__ void red_add_v2(float* p, float a, float b) {
    asm volatile("red.global.add.v2.f32 [%0], {%1, %2};"
                 :: "l"(p), "f"(a), "f"(b) : "memory");
}

__device__ __forceinline__ uint32_t smem_u32(const void* p) {
    uint32_t a;
    asm("{ .reg .u64 t; cvta.to.shared.u64 t, %1; cvt.u32.u64 %0, t; }" : "=r"(a) : "l"(p));
    return a;
}

#define LDSM_X4(r0, r1, r2, r3, addr) \
    asm volatile("ldmatrix.sync.aligned.m8n8.x4.shared.b16 {%0,%1,%2,%3}, [%4];" \
                 : "=r"(r0), "=r"(r1), "=r"(r2), "=r"(r3) : "r"(addr))

#define MMA16816(c, a, b0, b1) \
    asm volatile("mma.sync.aligned.m16n8k16.row.col.f32.bf16.bf16.f32 " \
                 "{%0,%1,%2,%3}, {%4,%5,%6,%7}, {%8,%9}, {%0,%1,%2,%3};" \
                 : "+f"((c)[0]), "+f"((c)[1]), "+f"((c)[2]), "+f"((c)[3]) \
                 : "r"((a)[0]), "r"((a)[1]), "r"((a)[2]), "r"((a)[3]), "r"(b0), "r"(b1))

#define CP_ASYNC16(dst, src) \
    asm volatile("cp.async.ca.shared.global [%0], [%1], 16;" :: "r"(dst), "l"(src))
#define CP_COMMIT() asm volatile("cp.async.commit_group;" ::: "memory")
#define CP_WAIT0()  asm volatile("cp.async.wait_group 0;" ::: "memory")

// ================= CSR build ====================================================
__global__ void zero_kernel() {
    int i = blockIdx.x * blockDim.x + threadIdx.x;
    if (i < NN) g_deg[i] = 0;
    if (i < NG * HID) g_pool[i] = 0.f;
}

__global__ void hist_kernel(const int* __restrict__ dst, int E) {
    int i = blockIdx.x * blockDim.x + threadIdx.x;
    int e = i * 4;
    if (e + 3 < E) {
        int4 d = ((const int4*)dst)[i];
        atomicAdd(&g_deg[d.x], 1);
        atomicAdd(&g_deg[d.y], 1);
        atomicAdd(&g_deg[d.z], 1);
        atomicAdd(&g_deg[d.w], 1);
    } else {
        for (; e < E; e++) atomicAdd(&g_deg[__ldg(dst + e)], 1);
    }
}

__global__ void scan_kernel() {
    __shared__ int part[1024];
    int t = threadIdx.x;
    const int CH = (NN + 1023) / 1024;
    int base = t * CH;
    int s = 0;
    #pragma unroll 8
    for (int i = 0; i < CH; i++) { int idx = base + i; if (idx < NN) s += g_deg[idx]; }
    part[t] = s;
    __syncthreads();
    for (int off = 1; off < 1024; off <<= 1) {
        int v = (t >= off) ? part[t - off] : 0;
        __syncthreads();
        part[t] += v;
        __syncthreads();
    }
    int run = (t == 0) ? 0 : part[t - 1];
    #pragma unroll 8
    for (int i = 0; i < CH; i++) {
        int idx = base + i;
        if (idx < NN) { g_off[idx] = run; g_cur[idx] = run; run += g_deg[idx]; }
    }
    if (t == 1023) g_off[NN] = run;
}

__global__ void fill_kernel(const int* __restrict__ src, const int* __restrict__ dst, int E) {
    int i = blockIdx.x * blockDim.x + threadIdx.x;
    int e = i * 4;
    if (e + 3 < E) {
        int4 s = ((const int4*)src)[i];
        int4 d = ((const int4*)dst)[i];
        int p0 = atomicAdd(&g_cur[d.x], 1);
        int p1 = atomicAdd(&g_cur[d.y], 1);
        int p2 = atomicAdd(&g_cur[d.z], 1);
        int p3 = atomicAdd(&g_cur[d.w], 1);
        g_srcs[p0] = s.x;
        g_srcs[p1] = s.y;
        g_srcs[p2] = s.z;
        g_srcs[p3] = s.w;
    } else {
        for (; e < E; e++) {
            int p = atomicAdd(&g_cur[__ldg(dst + e)], 1);
            g_srcs[p] = __ldg(src + e);
        }
    }
}

// ---------------- prep: fold embedding algebra + split/transpose weights -------
__global__ void prep_kernel(const float* __restrict__ embed_tab,
                            const float* __restrict__ W_pos,
                            const float* __restrict__ b_pos,
                            const float* __restrict__ W_comb,
                            const float* __restrict__ b_comb,
                            const float* __restrict__ W1all,
                            const float* __restrict__ W2all) {
    int j = threadIdx.x;
    int b = blockIdx.x;
    if (b < 100) {
        float acc = 0.f;
        #pragma unroll 8
        for (int i = 0; i < HID; i++)
            acc += embed_tab[b * HID + i] * W_comb[i * HID + j];
        g_EW[b * HID + j] = acc;
    } else if (b == 100) {
        float a0 = 0.f, a1 = 0.f, a2 = 0.f, ab = 0.f;
        #pragma unroll 8
        for (int i = 0; i < HID; i++) {
            float w = W_comb[(HID + i) * HID + j];
            a0 += W_pos[i] * w;
            a1 += W_pos[HID + i] * w;
            a2 += W_pos[2 * HID + i] * w;
            ab += b_pos[i] * w;
        }
        g_Wpc[j]           = a0;
        g_Wpc[HID + j]     = a1;
        g_Wpc[2 * HID + j] = a2;
        g_Wpc[3 * HID + j] = ab + b_comb[j];
    } else {
        int mat = b - 101;
        const float* W = ((mat & 1) ? W2all : W1all) + (size_t)(mat >> 1) * HID * HID;
        __nv_bfloat16* hi = g_whi + (size_t)mat * HID * HID;
        __nv_bfloat16* lo = g_wlo + (size_t)mat * HID * HID;
        #pragma unroll 4
        for (int k = 0; k < HID; k++) {
            float w = W[k * HID + j];
            __nv_bfloat16 hh = __float2bfloat16(w);
            hi[j * HID + k] = hh;
            lo[j * HID + k] = __float2bfloat16(w - __bfloat162float(hh));
        }
    }
}

// ---------------- x0 = relu(EW[z] + pos@Wpc + bfuse) ---------------------------
__global__ void x0_kernel(const int* __restrict__ z, const float* __restrict__ pos, int N) {
    int tid = blockIdx.x * blockDim.x + threadIdx.x;
    int n = tid >> 5;
    if (n >= N) return;
    int c = tid & 31;
    int zz = __ldg(z + n);
    float p0 = __ldg(pos + n * 3), p1 = __ldg(pos + n * 3 + 1), p2 = __ldg(pos + n * 3 + 2);
    float4 ew = *(const float4*)(g_EW + zz * HID + c * 4);
    float4 w0 = *(const float4*)(g_Wpc + c * 4);
    float4 w1 = *(const float4*)(g_Wpc + HID + c * 4);
    float4 w2 = *(const float4*)(g_Wpc + 2 * HID + c * 4);
    float4 bf = *(const float4*)(g_Wpc + 3 * HID + c * 4);
    float4 v;
    v.x = fmaxf(ew.x + p0 * w0.x + p1 * w1.x + p2 * w2.x + bf.x, 0.f);
    v.y = fmaxf(ew.y + p0 * w0.y + p1 * w1.y + p2 * w2.y + bf.y, 0.f);
    v.z = fmaxf(ew.z + p0 * w0.z + p1 * w1.z + p2 * w2.z + bf.z, 0.f);
    v.w = fmaxf(ew.w + p0 * w0.w + p1 * w1.w + p2 * w2.w + bf.w, 0.f);
    *(float4*)(g_x + n * HID + c * 4) = v;
}

// ---------------- CSR aggregation (fp32, 8-deep unroll) ------------------------
__global__ void agg_kernel(int N) {
    int tid = blockIdx.x * blockDim.x + threadIdx.x;
    int n = tid >> 5;
    if (n >= N) return;
    int lane = tid & 31;
    const float4* x4 = (const float4*)g_x;
    float4 a0 = x4[n * 32 + lane];
    float4 a1 = {0.f, 0.f, 0.f, 0.f};
    float4 a2 = {0.f, 0.f, 0.f, 0.f};
    float4 a3 = {0.f, 0.f, 0.f, 0.f};
    int beg = __ldg(&g_off[n]), end = __ldg(&g_off[n + 1]);
    int e = beg;
    for (; e + 8 <= end; e += 8) {
        int s0 = __ldg(&g_srcs[e]);
        int s1 = __ldg(&g_srcs[e + 1]);
        int s2 = __ldg(&g_srcs[e + 2]);
        int s3 = __ldg(&g_srcs[e + 3]);
        int s4 = __ldg(&g_srcs[e + 4]);
        int s5 = __ldg(&g_srcs[e + 5]);
        int s6 = __ldg(&g_srcs[e + 6]);
        int s7 = __ldg(&g_srcs[e + 7]);
        float4 v0 = x4[s0 * 32 + lane];
        float4 v1 = x4[s1 * 32 + lane];
        float4 v2 = x4[s2 * 32 + lane];
        float4 v3 = x4[s3 * 32 + lane];
        float4 v4 = x4[s4 * 32 + lane];
        float4 v5 = x4[s5 * 32 + lane];
        float4 v6 = x4[s6 * 32 + lane];
        float4 v7 = x4[s7 * 32 + lane];
        a0.x += v0.x; a0.y += v0.y; a0.z += v0.z; a0.w += v0.w;
        a1.x += v1.x; a1.y += v1.y; a1.z += v1.z; a1.w += v1.w;
        a2.x += v2.x; a2.y += v2.y; a2.z += v2.z; a2.w += v2.w;
        a3.x += v3.x; a3.y += v3.y; a3.z += v3.z; a3.w += v3.w;
        a0.x += v4.x; a0.y += v4.y; a0.z += v4.z; a0.w += v4.w;
        a1.x += v5.x; a1.y += v5.y; a1.z += v5.z; a1.w += v5.w;
        a2.x += v6.x; a2.y += v6.y; a2.z += v6.z; a2.w += v6.w;
        a3.x += v7.x; a3.y += v7.y; a3.z += v7.z; a3.w += v7.w;
    }
    for (; e < end; e++) {
        int s = __ldg(&g_srcs[e]);
        float4 v = x4[s * 32 + lane];
        a0.x += v.x; a0.y += v.y; a0.z += v.z; a0.w += v.w;
    }
    float4 r;
    r.x = a0.x + a1.x + a2.x + a3.x;
    r.y = a0.y + a1.y + a2.y + a3.y;
    r.z = a0.z + a1.z + a2.z + a3.z;
    r.w = a0.w + a1.w + a2.w + a3.w;
    ((float4*)g_h)[n * 32 + lane] = r;
}

// ========== PERSISTENT fused MLP (champion config: 128-row, 1 CTA/SM) ==========
#define PAD 136
#define TILE (128 * PAD * 2)
#define OFF_AHI 0
#define OFF_ALO TILE
#define OFF_W1H (2 * TILE)
#define OFF_W1L (3 * TILE)
#define OFF_W2H (4 * TILE)
#define OFF_W2L (5 * TILE)
#define SMEM_F  (6 * TILE)

template<int FINAL>
__global__ __launch_bounds__(256, 1)
void gemm_fused(const float* __restrict__ A,
                const __nv_bfloat16* __restrict__ W1h, const __nv_bfloat16* __restrict__ W1l,
                const __nv_bfloat16* __restrict__ W2h, const __nv_bfloat16* __restrict__ W2l,
                const float* __restrict__ b1, const float* __restrict__ b2,
                float* __restrict__ Cf, const int* __restrict__ batch,
                int M, int tiles) {
    extern __shared__ char smem[];
    uint32_t sb = smem_u32(smem);
    int t = threadIdx.x, wid = t >> 5, lane = t & 31;
    int warp_m = wid & 1, warp_n = wid >> 1;

    #pragma unroll
    for (int i = 0; i < 8; i++) {
        int idx = i * 256 + t;
        int n = idx >> 4, k8 = idx & 15;
        uint32_t off = (uint32_t)(n * PAD + k8 * 8) * 2;
        CP_ASYNC16(sb + OFF_W1H + off, (const char*)W1h + idx * 16);
        CP_ASYNC16(sb + OFF_W1L + off, (const char*)W1l + idx * 16);
        CP_ASYNC16(sb + OFF_W2H + off, (const char*)W2h + idx * 16);
        CP_ASYNC16(sb + OFF_W2L + off, (const char*)W2l + idx * 16);
    }
    CP_COMMIT();

    int a_r = warp_m * 64 + (lane & 15);
    int a_k = (lane >> 4) * 8;
    uint32_t aoff = (uint32_t)(a_r * PAD + a_k) * 2;
    int b_n = warp_n * 32 + (lane & 7) + ((lane >> 4) << 3);
    int b_k = ((lane >> 3) & 1) * 8;
    uint32_t boff = (uint32_t)(b_n * PAD + b_k) * 2;
    int g = lane >> 2, tq = lane & 3;

    bool first = true;

    for (int tile = blockIdx.x; tile < tiles; tile += gridDim.x) {
        int row0 = tile * 128;
        __syncthreads();

        #pragma unroll
        for (int i = 0; i < 8; i++) {
            int idx = i * 256 + t;
            int r = idx >> 4, k8 = idx & 15;
            int row = row0 + r;
            if (row >= M) row = M - 1;
            const float4* ap = (const float4*)(A + (size_t)row * HID + k8 * 8);
            float4 aA = ap[0], aB = ap[1];
            __nv_bfloat162 h0 = __floats2bfloat162_rn(aA.x, aA.y);
            __nv_bfloat162 h1 = __floats2bfloat162_rn(aA.z, aA.w);
            __nv_bfloat162 h2 = __floats2bfloat162_rn(aB.x, aB.y);
            __nv_bfloat162 h3 = __floats2bfloat162_rn(aB.z, aB.w);
            __nv_bfloat162 l0 = __floats2bfloat162_rn(aA.x - __bfloat162float(h0.x), aA.y - __bfloat162float(h0.y));
            __nv_bfloat162 l1 = __floats2bfloat162_rn(aA.z - __bfloat162float(h1.x), aA.w - __bfloat162float(h1.y));
            __nv_bfloat162 l2 = __floats2bfloat162_rn(aB.x - __bfloat162float(h2.x), aB.y - __bfloat162float(h2.y));
            __nv_bfloat162 l3 = __floats2bfloat162_rn(aB.z - __bfloat162float(h3.x), aB.w - __bfloat162float(h3.y));
            uint4 hv = {*(uint32_t*)&h0, *(uint32_t*)&h1, *(uint32_t*)&h2, *(uint32_t*)&h3};
            uint4 lv = {*(uint32_t*)&l0, *(uint32_t*)&l1, *(uint32_t*)&l2, *(uint32_t*)&l3};
            uint32_t off = (uint32_t)(r * PAD + k8 * 8) * 2;
            *(uint4*)(smem + OFF_AHI + off) = hv;
            *(uint4*)(smem + OFF_ALO + off) = lv;
        }
        if (first) { CP_WAIT0(); first = false; }
        __syncthreads();

        float acc[4][4][4];

        // ---- mainloop 1: h @ W1 ----
        #pragma unroll
        for (int i = 0; i < 4; i++)
            #pragma unroll
            for (int j = 0; j < 4; j++)
                acc[i][j][0] = acc[i][j][1] = acc[i][j][2] = acc[i][j][3] = 0.f;

        #pragma unroll
        for (int ks = 0; ks < 8; ks++) {
            uint32_t kb = (uint32_t)(ks * 16) * 2;
            uint32_t ah[4][4], al[4][4], bh[2][4], bl[2][4];
            #pragma unroll
            for (int mt = 0; mt < 4; mt++) {
                uint32_t ad = sb + aoff + (uint32_t)(mt * 16 * PAD) * 2 + kb;
                LDSM_X4(ah[mt][0], ah[mt][1], ah[mt][2], ah[mt][3], ad + OFF_AHI);
                LDSM_X4(al[mt][0], al[mt][1], al[mt][2], al[mt][3], ad + OFF_ALO);
            }
            #pragma unroll
            for (int nb = 0; nb < 2; nb++) {
                uint32_t bd = sb + boff + (uint32_t)(nb * 16 * PAD) * 2 + kb;
                LDSM_X4(bh[nb][0], bh[nb][1], bh[nb][2], bh[nb][3], bd + OFF_W1H);
                LDSM_X4(bl[nb][0], bl[nb][1], bl[nb][2], bl[nb][3], bd + OFF_W1L);
            }
            #pragma unroll
            for (int mt = 0; mt < 4; mt++) {
                #pragma unroll
                for (int nt = 0; nt < 4; nt++) {
                    int nb = nt >> 1, h = (nt & 1) * 2;
                    MMA16816(acc[mt][nt], ah[mt], bh[nb][h], bh[nb][h + 1]);
                    MMA16816(acc[mt][nt], ah[mt], bl[nb][h], bl[nb][h + 1]);
                    MMA16816(acc[mt][nt], al[mt], bh[nb][h], bh[nb][h + 1]);
                }
            }
        }

        // ---- bias1 + relu + split -> overwrite A buffers as T ----
        __syncthreads();
        #pragma unroll
        for (int mt = 0; mt < 4; mt++) {
            int rloc = warp_m * 64 + mt * 16 + g;
            #pragma unroll
            for (int nt = 0; nt < 4; nt++) {
                int col = warp_n * 32 + nt * 8 + tq * 2;
                float bx = __ldg(b1 + col), by = __ldg(b1 + col + 1);
                float v0 = fmaxf(acc[mt][nt][0] + bx, 0.f);
                float v1 = fmaxf(acc[mt][nt][1] + by, 0.f);
                float v2 = fmaxf(acc[mt][nt][2] + bx, 0.f);
                float v3 = fmaxf(acc[mt][nt][3] + by, 0.f);
                __nv_bfloat162 hA = __floats2bfloat162_rn(v0, v1);
                __nv_bfloat162 lA = __floats2bfloat162_rn(v0 - __bfloat162float(hA.x),
                                                          v1 - __bfloat162float(hA.y));
                __nv_bfloat162 hB = __floats2bfloat162_rn(v2, v3);
                __nv_bfloat162 lB = __floats2bfloat162_rn(v2 - __bfloat162float(hB.x),
                                                          v3 - __bfloat162float(hB.y));
                uint32_t o0 = (uint32_t)(rloc * PAD + col) * 2;
                uint32_t o1 = (uint32_t)((rloc + 8) * PAD + col) * 2;
                *(uint32_t*)(smem + OFF_AHI + o0) = *(uint32_t*)&hA;
                *(uint32_t*)(smem + OFF_ALO + o0) = *(uint32_t*)&lA;
                *(uint32_t*)(smem + OFF_AHI + o1) = *(uint32_t*)&hB;
                *(uint32_t*)(smem + OFF_ALO + o1) = *(uint32_t*)&lB;
            }
        }
        __syncthreads();

        // ---- mainloop 2: T @ W2 ----
        #pragma unroll
        for (int i = 0; i < 4; i++)
            #pragma unroll
            for (int j = 0; j < 4; j++)
                acc[i][j][0] = acc[i][j][1] = acc[i][j][2] = acc[i][j][3] = 0.f;

        #pragma unroll
        for (int ks = 0; ks < 8; ks++) {
            uint32_t kb = (uint32_t)(ks * 16) * 2;
            uint32_t ah[4][4], al[4][4], bh[2][4], bl[2][4];
            #pragma unroll
            for (int mt = 0; mt < 4; mt++) {
                uint32_t ad = sb + aoff + (uint32_t)(mt * 16 * PAD) * 2 + kb;
                LDSM_X4(ah[mt][0], ah[mt][1], ah[mt][2], ah[mt][3], ad + OFF_AHI);
                LDSM_X4(al[mt][0], al[mt][1], al[mt][2], al[mt][3], ad + OFF_ALO);
            }
            #pragma unroll
            for (int nb = 0; nb < 2; nb++) {
                uint32_t bd = sb + boff + (uint32_t)(nb * 16 * PAD) * 2 + kb;
                LDSM_X4(bh[nb][0], bh[nb][1], bh[nb][2], bh[nb][3], bd + OFF_W2H);
                LDSM_X4(bl[nb][0], bl[nb][1], bl[nb][2], bl[nb][3], bd + OFF_W2L);
            }
            #pragma unroll
            for (int mt = 0; mt < 4; mt++) {
                #pragma unroll
                for (int nt = 0; nt < 4; nt++) {
                    int nb = nt >> 1, h = (nt & 1) * 2;
                    MMA16816(acc[mt][nt], ah[mt], bh[nb][h], bh[nb][h + 1]);
                    MMA16816(acc[mt][nt], ah[mt], bl[nb][h], bl[nb][h + 1]);
                    MMA16816(acc[mt][nt], al[mt], bh[nb][h], bh[nb][h + 1]);
                }
            }
        }

        // ---- epilogue ----
        #pragma unroll
        for (int mt = 0; mt < 4; mt++) {
            int rbase = row0 + warp_m * 64 + mt * 16 + g;
            #pragma unroll
            for (int nt = 0; nt < 4; nt++) {
                int col = warp_n * 32 + nt * 8 + tq * 2;
                float bx = __ldg(b2 + col), by = __ldg(b2 + col + 1);
                float v0 = acc[mt][nt][0] + bx, v1 = acc[mt][nt][1] + by;
                float v2 = acc[mt][nt][2] + bx, v3 = acc[mt][nt][3] + by;
                if (FINAL == 0) {
                    v0 = fmaxf(v0, 0.f); v1 = fmaxf(v1, 0.f);
                    v2 = fmaxf(v2, 0.f); v3 = fmaxf(v3, 0.f);
                    if (rbase < M)
                        *(float2*)(Cf + (size_t)rbase * HID + col) = make_float2(v0, v1);
                    if (rbase + 8 < M)
                        *(float2*)(Cf + (size_t)(rbase + 8) * HID + col) = make_float2(v2, v3);
                } else {
                    if (rbase < M)
                        red_add_v2(g_pool + __ldg(batch + rbase) * HID + col, v0, v1);
                    if (rbase + 8 < M)
                        red_add_v2(g_pool + __ldg(batch + rbase + 8) * HID + col, v2, v3);
                }
            }
        }
    }
}

// ---------------- heads ---------------------------------------------------------
__global__ void heads_kernel(const float* __restrict__ W1, const float* __restrict__ b1,
                             const float* __restrict__ W2, const float* __restrict__ b2,
                             float* __restrict__ out) {
    __shared__ float sa[HID];
    __shared__ float red[HID];
    __shared__ float o[4];
    int g = blockIdx.x, j = threadIdx.x;
    sa[j] = g_pool[g * HID + j];
    __syncthreads();
    for (int k = 0; k < 4; k++) {
        float acc = b1[k * HID + j];
        const float* w = W1 + k * HID * HID + j;
        #pragma unroll 8
        for (int i = 0; i < HID; i++) acc += sa[i] * w[i * HID];
        acc = fmaxf(acc, 0.f);
        red[j] = acc * W2[k * HID + j];
        __syncthreads();
        for (int s = 64; s > 0; s >>= 1) {
            if (j < s) red[j] += red[j + s];
            __syncthreads();
        }
        if (j == 0) o[k] = red[0] + b2[k];
        __syncthreads();
    }
    if (j == 0) {
        float alpha = fmaxf(softplusf(o[0]) + 1.f, 1.f + 1e-4f);
        float beta  = softplusf(o[1]);
        float nu    = softplusf(o[2]);
        float gamma = o[3];
        float am1 = alpha - 1.f;
        out[g]            = gamma;
        out[NG + g]       = beta / am1;
        out[2 * NG + g]   = beta / (am1 * nu);
        out[3 * NG + g]   = nu;
        out[4 * NG + g]   = alpha;
        out[5 * NG + g]   = beta;
    }
}

// ---------------- driver --------------------------------------------------------
extern "C" void kernel_launch(void* const* d_in, const int* in_sizes, int n_in,
                              void* d_out, int out_size) {
    const int*   z        = (const int*)d_in[0];
    const float* pos      = (const float*)d_in[1];
    const int*   batch    = (const int*)d_in[2];
    const int*   eidx     = (const int*)d_in[3];
    const float* embed    = (const float*)d_in[4];
    const float* W_pos    = (const float*)d_in[5];
    const float* b_pos    = (const float*)d_in[6];
    const float* W_comb   = (const float*)d_in[7];
    const float* b_comb   = (const float*)d_in[8];
    const float* gin_W1   = (const float*)d_in[9];
    const float* gin_b1   = (const float*)d_in[10];
    const float* gin_W2   = (const float*)d_in[11];
    const float* gin_b2   = (const float*)d_in[12];
    const float* head_W1  = (const float*)d_in[13];
    const float* head_b1  = (const float*)d_in[14];
    const float* head_W2  = (const float*)d_in[15];
    const float* head_b2  = (const float*)d_in[16];
    float* out = (float*)d_out;

    const int N = in_sizes[0];
    const int E = in_sizes[3] / 2;
    const int* src = eidx;
    const int* dst = eidx + E;

    float *x, *h;
    __nv_bfloat16 *whi, *wlo;
    cudaGetSymbolAddress((void**)&x, g_x);
    cudaGetSymbolAddress((void**)&h, g_h);
    cudaGetSymbolAddress((void**)&whi, g_whi);
    cudaGetSymbolAddress((void**)&wlo, g_wlo);

    cudaFuncSetAttribute(gemm_fused<0>, cudaFuncAttributeMaxDynamicSharedMemorySize, SMEM_F);
    cudaFuncSetAttribute(gemm_fused<1>, cudaFuncAttributeMaxDynamicSharedMemorySize, SMEM_F);

    // 1. zeros + CSR build + weight prep + x0 (champion R10 setup chain)
    const int zmax = (NG * HID > NN) ? NG * HID : NN;
    zero_kernel<<<(zmax + 255) / 256, 256>>>();
    hist_kernel<<<((E + 3) / 4 + 255) / 256, 256>>>(dst, E);
    scan_kernel<<<1, 1024>>>();
    fill_kernel<<<((E + 3) / 4 + 255) / 256, 256>>>(src, dst, E);
    prep_kernel<<<109, 128>>>(embed, W_pos, b_pos, W_comb, b_comb, gin_W1, gin_W2);
    x0_kernel<<<(N * 32 + 255) / 256, 256>>>(z, pos, N);

    // 2. GIN layers (agg + persistent fused MLP, champion config)
    const int tiles = (N + 127) / 128;
    const int pblocks = (tiles < 148) ? tiles : 148;
    const int agg_blocks = (N * 32 + 255) / 256;
    for (int l = 0; l < 4; l++) {
        agg_kernel<<<agg_blocks, 256>>>(N);
        const __nv_bfloat16* w1h = whi + (size_t)(2 * l) * HID * HID;
        const __nv_bfloat16* w1l = wlo + (size_t)(2 * l) * HID * HID;
        const __nv_bfloat16* w2h = whi + (size_t)(2 * l + 1) * HID * HID;
        const __nv_bfloat16* w2l = wlo + (size_t)(2 * l + 1) * HID * HID;
        if (l < 3)
            gemm_fused<0><<<pblocks, 256, SMEM_F>>>(h, w1h, w1l, w2h, w2l,
                                                    gin_b1 + l * HID, gin_b2 + l * HID,
                                                    x, nullptr, N, tiles);
        else
            gemm_fused<1><<<pblocks, 256, SMEM_F>>>(h, w1h, w1l, w2h, w2l,
                                                    gin_b1 + l * HID, gin_b2 + l * HID,
                                                    nullptr, batch, N, tiles);
    }

    // 3. heads
    heads_kernel<<<NG, 128>>>(head_W1, head_b1, head_W2, head_b2, out);
}